// round 3
// baseline (speedup 1.0000x reference)
#include <cuda_runtime.h>
#include <math.h>

// ---------------- problem constants ----------------
#define NN   512
#define BB   2
#define DD   128
#define OO   16
#define HH   64
#define CHN  48
#define CUMSZ (513*256)           // [513][B][D]
#define SPRE_SZ (2*16*512*512)    // [B][O][512][512]
#define H1_SZ   (2*48*514*516)    // [B][CH][514][516]  (row-padded to 516)
#define S_OUT_SZ (512*512*2*16)   // 8388608
#define PAIR_ROWS (131328*2)      // 262656
#define SKIP_ROWS (511*2)         // 1022
#define PAIR_BLOCKS (PAIR_ROWS/64)   // 4104
#define SKIP_BLOCKS 16

typedef unsigned long long ull;

__device__ float g_cum[3*CUMSZ];
__device__ float g_Spre[SPRE_SZ];
__device__ float g_H1[H1_SZ];

__device__ __forceinline__ float gelu_f(float v) {
    return 0.5f*v*(1.0f + erff(v*0.70710678118654752440f));
}
__device__ __forceinline__ ull pk2(float a, float b) {
    ull r; asm("mov.b64 %0,{%1,%2};" : "=l"(r) : "f"(a), "f"(b)); return r;
}
__device__ __forceinline__ void fma2(ull& d, ull a, ull b) {
    asm("fma.rn.f32x2 %0,%1,%2,%0;" : "+l"(d) : "l"(a), "l"(b));
}
__device__ __forceinline__ void upk2(ull v, float& a, float& b) {
    asm("mov.b64 {%0,%1},%2;" : "=f"(a), "=f"(b) : "l"(v));
}

// ---------------- prefix sums of x, x^2, x^3 ----------------
__global__ void prefix_kernel(const float* __restrict__ x) {
    int t = threadIdx.x;              // 256 = B*D columns
    float s1 = 0.f, s2 = 0.f, s3 = 0.f;
    g_cum[t] = 0.f; g_cum[CUMSZ + t] = 0.f; g_cum[2*CUMSZ + t] = 0.f;
    for (int n = 0; n < NN; ++n) {
        float v = x[n*256 + t];
        float v2 = v*v;
        s1 += v; s2 += v2; s3 += v2*v;
        int o = (n+1)*256 + t;
        g_cum[o] = s1; g_cum[CUMSZ + o] = s2; g_cum[2*CUMSZ + o] = s3;
    }
}

// ---------------- fused feature-gen + 3-layer MLP (tiled GEMM, f32x2) ----------------
// 64 rows per block, 256 threads, 16x16 thread grid, 4x4 micro-tile (packed row-pairs).
// blocks [0, PAIR_BLOCKS) = pair MLP (KIN=768); blocks [PAIR_BLOCKS, +16) = skip MLP (KIN=384).
__global__ __launch_bounds__(256) void mlp_kernel(
    const float* __restrict__ x,
    const float* __restrict__ w1, const float* __restrict__ b1,
    const float* __restrict__ w2, const float* __restrict__ b2,
    const float* __restrict__ w3, const float* __restrict__ b3,
    const float* __restrict__ sw1, const float* __restrict__ sb1v,
    const float* __restrict__ sw2, const float* __restrict__ sb2v,
    const float* __restrict__ sw3, const float* __restrict__ sb3v,
    float* __restrict__ outSkip)
{
    __shared__ float sA [32*68];    // A-tile  [32 k][64 row] (+pad)
    __shared__ float sBd[32*136];   // B-tile duplicated: [32 k][64 col x2]
    __shared__ float sH [64*68];    // hidden activations, [unit][row]
    __shared__ int   sXI[64], sXJ[64], sCI[64], sCJ[64], sOut[64];
    __shared__ float sInv[64], sb1[64], sb2[64], sb3[16];

    const int  tid    = threadIdx.x;
    const int  ty4    = (tid >> 4) * 4;
    const int  tx4    = (tid & 15) * 4;
    const bool isSkip = (blockIdx.x >= PAIR_BLOCKS);
    const int  nch    = isSkip ? 12 : 24;

    const float* pw1 = isSkip ? sw1 : w1;
    const float* pw2 = isSkip ? sw2 : w2;
    const float* pw3 = isSkip ? sw3 : w3;
    const int    kin = isSkip ? 384 : 768;

    if (tid < 64) {
        if (!isSkip) {
            int r = blockIdx.x*64 + tid;
            int p = r >> 1, b = r & 1;
            int i = (int)((sqrt(8.0*(double)p + 1.0) - 1.0)*0.5);
            while ((i+1)*(i+2)/2 <= p) ++i;
            while (i*(i+1)/2 > p) --i;
            int j = p - i*(i+1)/2;
            sXI[tid]  = i*256 + b*128;
            sXJ[tid]  = j*256 + b*128;
            sCI[tid]  = (i+1)*256 + b*128;
            sCJ[tid]  = j*256 + b*128;
            sInv[tid] = 1.0f/(float)(i - j + 1);
            sOut[tid] = b*4194304 + i*512 + j;   // b*16*512*512; + o*262144 later
        } else {
            int r = (blockIdx.x - PAIR_BLOCKS)*64 + tid;
            if (r >= SKIP_ROWS) r = SKIP_ROWS - 1;
            int p = r >> 1, b = r & 1;
            sXI[tid]  = p*256 + b*128;           // x[t]
            sXJ[tid]  = (p+1)*256 + b*128;       // x[t+1]
            sInv[tid] = 1.0f;
            sOut[tid] = r*16;
        }
        sb1[tid] = isSkip ? sb1v[tid] : b1[tid];
        sb2[tid] = isSkip ? sb2v[tid] : b2[tid];
        if (tid < 16) sb3[tid] = isSkip ? sb3v[tid] : b3[tid];
    }

    // -------- layer 1: [64 x KIN] @ w1^T -> [64 x 64] --------
    ull acc[2][4] = {};      // [row-pair][col]; each ull = (row 2rp, row 2rp+1)
    for (int kc = 0; kc < nch; ++kc) {
        const int k0  = kc*32;
        const int seg = k0 >> 7;
        const int d0  = k0 & 127;
        if (kc) __syncthreads();                  // protect sA/sBd overwrite
        else    __syncthreads();                  // index setup visible
        #pragma unroll
        for (int e = 0; e < 8; ++e) {             // generate A chunk [64 rows][32 k]
            int idx = tid + e*256;
            int row = idx >> 5, kk = idx & 31;
            int d = d0 + kk;
            float v;
            if (seg == 0)      v = x[sXI[row] + d];
            else if (seg == 1) v = x[sXJ[row] + d];
            else if (seg == 2) v = x[sXI[row] + d] * x[sXJ[row] + d];
            else {
                const float* c0 = g_cum + (seg-3)*CUMSZ;
                v = (c0[sCI[row] + d] - c0[sCJ[row] + d]) * sInv[row];
            }
            sA[kk*68 + row] = v;
        }
        #pragma unroll
        for (int e = 0; e < 8; ++e) {             // load w1 chunk, duplicated pairs
            int idx = tid + e*256;
            int col = idx >> 5, kk = idx & 31;
            float w = pw1[col*kin + k0 + kk];
            *(ull*)&sBd[kk*136 + col*2] = pk2(w, w);
        }
        __syncthreads();
        #pragma unroll
        for (int kk = 0; kk < 32; ++kk) {
            ull a01 = *(const ull*)&sA[kk*68 + ty4];
            ull a23 = *(const ull*)&sA[kk*68 + ty4 + 2];
            const ull* bp = (const ull*)&sBd[kk*136 + tx4*2];
            #pragma unroll
            for (int c = 0; c < 4; ++c) {
                ull bd = bp[c];
                fma2(acc[0][c], a01, bd);
                fma2(acc[1][c], a23, bd);
            }
        }
    }
    __syncthreads();
    // bias + gelu -> sH [unit][row]
    #pragma unroll
    for (int c = 0; c < 4; ++c) {
        float bias = sb1[tx4 + c];
        #pragma unroll
        for (int rp = 0; rp < 2; ++rp) {
            float lo, hi; upk2(acc[rp][c], lo, hi);
            sH[(tx4 + c)*68 + ty4 + 2*rp    ] = gelu_f(lo + bias);
            sH[(tx4 + c)*68 + ty4 + 2*rp + 1] = gelu_f(hi + bias);
        }
    }

    // -------- layer 2: [64 x 64] @ w2^T -> [64 x 64], two k-chunks --------
    ull acc2[2][4] = {};
    #pragma unroll
    for (int kh = 0; kh < 2; ++kh) {
        __syncthreads();
        #pragma unroll
        for (int e = 0; e < 8; ++e) {
            int idx = tid + e*256;
            int col = idx >> 5, kk = idx & 31;
            float w = pw2[col*64 + kh*32 + kk];
            *(ull*)&sBd[kk*136 + col*2] = pk2(w, w);
        }
        __syncthreads();
        #pragma unroll
        for (int kk = 0; kk < 32; ++kk) {
            ull a01 = *(const ull*)&sH[(kh*32 + kk)*68 + ty4];
            ull a23 = *(const ull*)&sH[(kh*32 + kk)*68 + ty4 + 2];
            const ull* bp = (const ull*)&sBd[kk*136 + tx4*2];
            #pragma unroll
            for (int c = 0; c < 4; ++c) {
                ull bd = bp[c];
                fma2(acc2[0][c], a01, bd);
                fma2(acc2[1][c], a23, bd);
            }
        }
    }
    __syncthreads();
    #pragma unroll
    for (int c = 0; c < 4; ++c) {
        float bias = sb2[tx4 + c];
        #pragma unroll
        for (int rp = 0; rp < 2; ++rp) {
            float lo, hi; upk2(acc2[rp][c], lo, hi);
            sH[(tx4 + c)*68 + ty4 + 2*rp    ] = gelu_f(lo + bias);
            sH[(tx4 + c)*68 + ty4 + 2*rp + 1] = gelu_f(hi + bias);
        }
    }
    // -------- layer 3: [64 x 64] @ w3^T -> [64 x 16] --------
    float* sW3 = sBd;                 // reuse: [64 k][16 col]
    #pragma unroll
    for (int e = 0; e < 4; ++e) {
        int idx = tid + e*256;        // 1024 elems
        int col = idx & 15, kk = idx >> 4;
        sW3[kk*16 + col] = pw3[col*64 + kk];
    }
    __syncthreads();
    const int row = tid >> 2;
    const int cg  = (tid & 3)*4;
    ull o01 = 0, o23 = 0;
    #pragma unroll
    for (int kk = 0; kk < 64; ++kk) {
        float a  = sH[kk*68 + row];
        ull   ad = pk2(a, a);
        fma2(o01, ad, *(const ull*)&sW3[kk*16 + cg]);
        fma2(o23, ad, *(const ull*)&sW3[kk*16 + cg + 2]);
    }
    float o[4];
    upk2(o01, o[0], o[1]); upk2(o23, o[2], o[3]);
    if (!isSkip) {
        int base = sOut[row];
        #pragma unroll
        for (int c = 0; c < 4; ++c)
            g_Spre[base + (cg + c)*262144] = o[c] + sb3[cg + c];
    } else {
        int rg = (blockIdx.x - PAIR_BLOCKS)*64 + row;
        if (rg < SKIP_ROWS) {
            int base = sOut[row];
            #pragma unroll
            for (int c = 0; c < 4; ++c)
                outSkip[base + cg + c] = o[c] + sb3[cg + c];
        }
    }
}

// ---------------- conv1: 16 -> 48, 3x3, pad 2, + GELU (f32x2, oc-pairs) ----------------
// grid (9, 33, 8): z = b*4 + oc-group(12). Tile 16y x 64x, thread does 4 x-pixels.
__global__ __launch_bounds__(256) void conv1_kernel(
    const float* __restrict__ cw1, const float* __restrict__ cb1)
{
    extern __shared__ float smem[];
    float* sIn = smem;                 // [16][18][68]
    float* sW  = smem + 16*18*68;      // [(c*9+k)][12 oc]
    const int tid = threadIdx.x;
    const int b = blockIdx.z >> 2, g = blockIdx.z & 3;
    const int by = blockIdx.y, bx = blockIdx.x;
    const int ty = tid >> 4, tx = tid & 15;

    for (int idx = tid; idx < 16*18*66; idx += 256) {
        int c  = idx / 1188;
        int rem = idx - c*1188;
        int sy = rem / 66, sx = rem - sy*66;
        int iy = by*16 + sy - 2;
        int ix = bx*64 + sx - 2;
        float v = 0.f;
        if (iy >= 0 && iy < 512 && ix >= 0 && ix < 512 && iy >= ix)   // lower triangle only
            v = g_Spre[((b*16 + c) << 18) + (iy << 9) + ix];
        sIn[(c*18 + sy)*68 + sx] = v;
    }
    for (int idx = tid; idx < 12*16*9; idx += 256) {
        int oc = idx % 12, rest = idx / 12;     // rest = c*9 + k
        int k = rest % 9, c = rest / 9;
        sW[idx] = cw1[((g*12 + oc)*16 + c)*9 + k];
    }
    __syncthreads();

    ull accP[6][4] = {};   // [oc-pair][px]
    #pragma unroll 1
    for (int c = 0; c < 16; ++c) {
        #pragma unroll
        for (int ky = 0; ky < 3; ++ky) {
            const float* rp = &sIn[(c*18 + ty + ky)*68 + tx*4];
            float4 v4 = *(const float4*)rp;
            float vv[6] = {v4.x, v4.y, v4.z, v4.w, rp[4], rp[5]};
            ull vd[6];
            #pragma unroll
            for (int m = 0; m < 6; ++m) vd[m] = pk2(vv[m], vv[m]);
            #pragma unroll
            for (int kx = 0; kx < 3; ++kx) {
                const float* wb = &sW[(c*9 + ky*3 + kx)*12];
                #pragma unroll
                for (int op = 0; op < 6; ++op) {
                    ull wp = *(const ull*)&wb[op*2];
                    fma2(accP[op][0], wp, vd[kx + 0]);
                    fma2(accP[op][1], wp, vd[kx + 1]);
                    fma2(accP[op][2], wp, vd[kx + 2]);
                    fma2(accP[op][3], wp, vd[kx + 3]);
                }
            }
        }
    }
    int oy = by*16 + ty;
    int ox0 = bx*64 + tx*4;
    if (oy < 514) {
        #pragma unroll
        for (int op = 0; op < 6; ++op) {
            int oc0 = g*12 + op*2;
            float bias0 = cb1[oc0], bias1 = cb1[oc0 + 1];
            float r0[4], r1[4];
            #pragma unroll
            for (int px = 0; px < 4; ++px) {
                float lo, hi; upk2(accP[op][px], lo, hi);
                r0[px] = gelu_f(lo + bias0);
                r1[px] = gelu_f(hi + bias1);
            }
            long base0 = ((long)(b*48 + oc0    )*514 + oy)*516 + ox0;
            long base1 = ((long)(b*48 + oc0 + 1)*514 + oy)*516 + ox0;
            if (ox0 + 3 < 514) {
                *(float4*)&g_H1[base0] = make_float4(r0[0], r0[1], r0[2], r0[3]);
                *(float4*)&g_H1[base1] = make_float4(r1[0], r1[1], r1[2], r1[3]);
            } else {
                #pragma unroll
                for (int px = 0; px < 4; ++px)
                    if (ox0 + px < 514) { g_H1[base0 + px] = r0[px]; g_H1[base1 + px] = r1[px]; }
            }
        }
    }
}

// ---------------- conv2: 48 -> 16, 3x3 valid, + bias + length-scale + store (f32x2) ----------------
// grid (8, 32, 2): z = b. Tile 16y x 64x of 512x512.
__global__ __launch_bounds__(256) void conv2_kernel(
    const float* __restrict__ cw2, const float* __restrict__ cb2,
    float* __restrict__ out)
{
    extern __shared__ float smem[];
    float* sIn = smem;                 // [12][18][68]
    float* sW  = smem + 12*18*68;      // [(c48*9+k)][16 oc]
    const int tid = threadIdx.x;
    const int b = blockIdx.z;
    const int by = blockIdx.y, bx = blockIdx.x;
    const int ty = tid >> 4, tx = tid & 15;

    for (int idx = tid; idx < 16*48*9; idx += 256) {
        int oc = idx % 16, rest = idx / 16;   // rest = c48*9 + k
        int k = rest % 9, c48 = rest / 9;
        sW[idx] = cw2[(oc*48 + c48)*9 + k];
    }

    ull accP[8][4] = {};   // [oc-pair][px]
    for (int cc = 0; cc < 4; ++cc) {
        __syncthreads();
        for (int idx = tid; idx < 12*18*66; idx += 256) {
            int c  = idx / 1188;
            int rem = idx - c*1188;
            int sy = rem / 66, sx = rem - sy*66;
            sIn[(c*18 + sy)*68 + sx] =
                g_H1[((long)(b*48 + cc*12 + c)*514 + by*16 + sy)*516 + bx*64 + sx];
        }
        __syncthreads();
        #pragma unroll 1
        for (int c = 0; c < 12; ++c) {
            #pragma unroll
            for (int ky = 0; ky < 3; ++ky) {
                const float* rp = &sIn[(c*18 + ty + ky)*68 + tx*4];
                float4 v4 = *(const float4*)rp;
                float vv[6] = {v4.x, v4.y, v4.z, v4.w, rp[4], rp[5]};
                ull vd[6];
                #pragma unroll
                for (int m = 0; m < 6; ++m) vd[m] = pk2(vv[m], vv[m]);
                #pragma unroll
                for (int kx = 0; kx < 3; ++kx) {
                    const float* wb = &sW[((cc*12 + c)*9 + ky*3 + kx)*16];
                    #pragma unroll
                    for (int op = 0; op < 8; ++op) {
                        ull wp = *(const ull*)&wb[op*2];
                        fma2(accP[op][0], wp, vd[kx + 0]);
                        fma2(accP[op][1], wp, vd[kx + 1]);
                        fma2(accP[op][2], wp, vd[kx + 2]);
                        fma2(accP[op][3], wp, vd[kx + 3]);
                    }
                }
            }
        }
    }
    int oy = by*16 + ty;
    int ox0 = bx*64 + tx*4;
    float bias[16];
    #pragma unroll
    for (int oc = 0; oc < 16; ++oc) bias[oc] = cb2[oc];
    #pragma unroll
    for (int px = 0; px < 4; ++px) {
        int ox = ox0 + px;
        int ad = oy - ox; if (ad < 0) ad = -ad; if (ad < 1) ad = 1;
        float len = (float)ad;
        float o[16];
        #pragma unroll
        for (int op = 0; op < 8; ++op) {
            float lo, hi; upk2(accP[op][px], lo, hi);
            o[op*2]     = len*(lo + bias[op*2]);
            o[op*2 + 1] = len*(hi + bias[op*2 + 1]);
        }
        float4* ob = (float4*)(out + ((long)(oy*512 + ox)*2 + b)*16);
        ob[0] = make_float4(o[0],  o[1],  o[2],  o[3]);
        ob[1] = make_float4(o[4],  o[5],  o[6],  o[7]);
        ob[2] = make_float4(o[8],  o[9],  o[10], o[11]);
        ob[3] = make_float4(o[12], o[13], o[14], o[15]);
    }
}

// ---------------- launch ----------------
extern "C" void kernel_launch(void* const* d_in, const int* in_sizes, int n_in,
                              void* d_out, int out_size)
{
    const float* x   = (const float*)d_in[0];
    const float* w1  = (const float*)d_in[1];
    const float* b1  = (const float*)d_in[2];
    const float* w2  = (const float*)d_in[3];
    const float* b2  = (const float*)d_in[4];
    const float* w3  = (const float*)d_in[5];
    const float* b3  = (const float*)d_in[6];
    const float* sw1 = (const float*)d_in[7];
    const float* sb1 = (const float*)d_in[8];
    const float* sw2 = (const float*)d_in[9];
    const float* sb2 = (const float*)d_in[10];
    const float* sw3 = (const float*)d_in[11];
    const float* sb3 = (const float*)d_in[12];
    const float* cw1 = (const float*)d_in[13];
    const float* cb1 = (const float*)d_in[14];
    const float* cw2 = (const float*)d_in[15];
    const float* cb2 = (const float*)d_in[16];
    float* out = (float*)d_out;

    const int c1_smem = (16*18*68 + 12*16*9)*4;
    const int c2_smem = (12*18*68 + 16*48*9)*4;
    static bool attr_done = false;
    if (!attr_done) {
        cudaFuncSetAttribute(conv1_kernel, cudaFuncAttributeMaxDynamicSharedMemorySize, c1_smem);
        cudaFuncSetAttribute(conv2_kernel, cudaFuncAttributeMaxDynamicSharedMemorySize, c2_smem);
        attr_done = true;
    }

    prefix_kernel<<<1, 256>>>(x);
    mlp_kernel<<<PAIR_BLOCKS + SKIP_BLOCKS, 256>>>(x, w1, b1, w2, b2, w3, b3,
                                                   sw1, sb1, sw2, sb2, sw3, sb3,
                                                   out + S_OUT_SZ);
    conv1_kernel<<<dim3(9, 33, 8), 256, c1_smem>>>(cw1, cb1);
    conv2_kernel<<<dim3(8, 32, 2), 256, c2_smem>>>(cw2, cb2, out);
}

// round 8
// speedup vs baseline: 1.7232x; 1.7232x over previous
#include <cuda_runtime.h>
#include <cuda_bf16.h>
#include <cstdint>
#include <math.h>

// ---------------- problem constants ----------------
#define NN   512
#define CUMSZ (513*256)           // [513][B][D]
#define SPRE_SZ (2*16*512*512)    // [B][O][512][512]
#define H1_SZ   (2*48*514*516)    // [B][CH][514][516]
#define S_OUT_SZ (512*512*2*16)
#define PAIR_ROWS 262656
#define PAIR_BLOCKS (PAIR_ROWS/128)   // 2052
#define SKIP_ROWS 1022
#define AST 36                       // A/B smem row stride in u32

__device__ float g_cum[3*CUMSZ];
__device__ float g_Spre[SPRE_SZ];
__device__ float g_H1[H1_SZ];
// prepped w1: bf16 hi/lo, [chunk][hl][n][k]
__device__ __align__(16) __nv_bfloat16 g_w1p[6*2*64*64];

__device__ __forceinline__ float gelu_f(float v) {
    return 0.5f*v*(1.0f + erff(v*0.70710678118654752440f));
}

__device__ __forceinline__ void split2(float v0, float v1, uint32_t& hi, uint32_t& lo) {
    __nv_bfloat16 h0 = __float2bfloat16(v0);
    __nv_bfloat16 h1 = __float2bfloat16(v1);
    float h0f = __uint_as_float(((uint32_t)__bfloat16_as_ushort(h0)) << 16);
    float h1f = __uint_as_float(((uint32_t)__bfloat16_as_ushort(h1)) << 16);
    __nv_bfloat16 l0 = __float2bfloat16(v0 - h0f);
    __nv_bfloat16 l1 = __float2bfloat16(v1 - h1f);
    hi = (uint32_t)__bfloat16_as_ushort(h0) | ((uint32_t)__bfloat16_as_ushort(h1) << 16);
    lo = (uint32_t)__bfloat16_as_ushort(l0) | ((uint32_t)__bfloat16_as_ushort(l1) << 16);
}

__device__ __forceinline__ void mma16816(float* d, const uint32_t* a, uint32_t b0, uint32_t b1) {
    asm volatile("mma.sync.aligned.m16n8k16.row.col.f32.bf16.bf16.f32 "
        "{%0,%1,%2,%3}, {%4,%5,%6,%7}, {%8,%9}, {%0,%1,%2,%3};"
        : "+f"(d[0]), "+f"(d[1]), "+f"(d[2]), "+f"(d[3])
        : "r"(a[0]), "r"(a[1]), "r"(a[2]), "r"(a[3]), "r"(b0), "r"(b1));
}

// 3-pass (Ah*Bh + Ah*Bl + Al*Bh) MMA over one K=64 chunk: 32x32 per warp
__device__ __forceinline__ void mma_block(
    float acc[2][4][4],
    const uint32_t* sAh, const uint32_t* sAl,
    const uint32_t* sBh, const uint32_t* sBl,
    int mbase, int nbase, int g, int tg)
{
    #pragma unroll
    for (int pass = 0; pass < 3; ++pass) {
        const uint32_t* A = (pass == 2) ? sAl : sAh;
        const uint32_t* B = (pass == 1) ? sBl : sBh;
        #pragma unroll
        for (int kt = 0; kt < 4; ++kt) {
            uint32_t af[2][4];
            #pragma unroll
            for (int mi = 0; mi < 2; ++mi) {
                int r0 = (mbase + mi*16 + g)*AST + kt*8 + tg;
                af[mi][0] = A[r0];
                af[mi][1] = A[r0 + 8*AST];
                af[mi][2] = A[r0 + 4];
                af[mi][3] = A[r0 + 8*AST + 4];
            }
            #pragma unroll
            for (int ni = 0; ni < 4; ++ni) {
                int rb = (nbase + ni*8 + g)*AST + kt*8 + tg;
                uint32_t b0 = B[rb], b1 = B[rb + 4];
                mma16816(acc[0][ni], af[0], b0, b1);
                mma16816(acc[1][ni], af[1], b0, b1);
            }
        }
    }
}

// ---------------- prefix sums of x, x^2, x^3 ----------------
__global__ void prefix_kernel(const float* __restrict__ x) {
    int t = threadIdx.x;
    float s1 = 0.f, s2 = 0.f, s3 = 0.f;
    g_cum[t] = 0.f; g_cum[CUMSZ + t] = 0.f; g_cum[2*CUMSZ + t] = 0.f;
    for (int n = 0; n < NN; ++n) {
        float v = x[n*256 + t];
        float v2 = v*v;
        s1 += v; s2 += v2; s3 += v2*v;
        int o = (n+1)*256 + t;
        g_cum[o] = s1; g_cum[CUMSZ + o] = s2; g_cum[2*CUMSZ + o] = s3;
    }
}

// ---------------- weight prep: w1 fp32 -> bf16 hi/lo ----------------
__global__ void prep_w_kernel(const float* __restrict__ w1) {
    int i0 = blockIdx.x*blockDim.x + threadIdx.x;
    int stride = gridDim.x*blockDim.x;
    for (int idx = i0; idx < 64*768; idx += stride) {
        int n = idx / 768, k = idx % 768;
        int ch = k >> 6, kk = k & 63;
        float v = w1[idx];
        __nv_bfloat16 h = __float2bfloat16(v);
        float hf = __uint_as_float(((uint32_t)__bfloat16_as_ushort(h)) << 16);
        __nv_bfloat16 l = __float2bfloat16(v - hf);
        g_w1p[((ch*2 + 0)*64 + n)*64 + kk] = h;
        g_w1p[((ch*2 + 1)*64 + n)*64 + kk] = l;
    }
}

// ---------------- pair MLP: HMMA layer 1 + scalar fp32 layers 2-3 ----------------
// smem u32 offsets
#define O_AH 0
#define O_AL (O_AH + 128*AST)
#define O_BH (O_AL + 128*AST)
#define O_BL (O_BH + 64*AST)
#define O_XI (O_BL + 64*AST)
#define O_XJ (O_XI + 128)
#define O_CI (O_XJ + 128)
#define O_CJ (O_CI + 128)
#define O_OUT (O_CJ + 128)
#define O_INV (O_OUT + 128)
#define O_B1 (O_INV + 128)
#define O_B2 (O_B1 + 64)
#define O_B3 (O_B2 + 64)
#define O_W2T (O_B3 + 16)          // fp32 [k][64]  (4096)
#define O_W3T (O_W2T + 4096)       // fp32 [k][16]  (1024)
#define MMA_SMEM_U32 (O_W3T + 1024)

__global__ __launch_bounds__(256) void pair_mma_kernel(
    const float* __restrict__ x,
    const float* __restrict__ b1, const float* __restrict__ b2, const float* __restrict__ b3,
    const float* __restrict__ w2, const float* __restrict__ w3)
{
    extern __shared__ uint32_t sm[];
    uint32_t* sAh = sm + O_AH;
    uint32_t* sAl = sm + O_AL;
    uint32_t* sBh = sm + O_BH;
    uint32_t* sBl = sm + O_BL;
    float* sHf = (float*)(sm + O_AH);   // alias: fp32 H1 [128][68] after L1
    int*   sXI = (int*)(sm + O_XI);
    int*   sXJ = (int*)(sm + O_XJ);
    int*   sCI = (int*)(sm + O_CI);
    int*   sCJ = (int*)(sm + O_CJ);
    int*   sOut = (int*)(sm + O_OUT);
    float* sInv = (float*)(sm + O_INV);
    float* sb1 = (float*)(sm + O_B1);
    float* sb2 = (float*)(sm + O_B2);
    float* sb3 = (float*)(sm + O_B3);
    float* sW2T = (float*)(sm + O_W2T);
    float* sW3T = (float*)(sm + O_W3T);

    const int tid = threadIdx.x;
    const int wid = tid >> 5;
    const int lane = tid & 31;
    const int g = lane >> 2;
    const int tg = lane & 3;
    const int wm = wid & 3;
    const int wn = wid >> 2;
    const int mbase = wm*32;
    const int nbase = wn*32;

    if (tid < 128) {
        int r = blockIdx.x*128 + tid;
        int p = r >> 1, b = r & 1;
        int i = (int)((sqrt(8.0*(double)p + 1.0) - 1.0)*0.5);
        while ((i+1)*(i+2)/2 <= p) ++i;
        while (i*(i+1)/2 > p) --i;
        int j = p - i*(i+1)/2;
        sXI[tid] = i*256 + b*128;
        sXJ[tid] = j*256 + b*128;
        sCI[tid] = (i+1)*256 + b*128;
        sCJ[tid] = j*256 + b*128;
        sInv[tid] = 1.0f/(float)(i - j + 1);
        sOut[tid] = b*4194304 + i*512 + j;
    }
    if (tid < 64) { sb1[tid] = b1[tid]; sb2[tid] = b2[tid]; }
    if (tid >= 64 && tid < 80) sb3[tid - 64] = b3[tid - 64];
    // load w2/w3 transposed (fp32): sW2T[k*64+u] = w2[u*64+k]
    for (int idx = tid; idx < 4096; idx += 256) {
        int u = idx >> 6, k = idx & 63;
        sW2T[k*64 + u] = w2[idx];
    }
    for (int idx = tid; idx < 1024; idx += 256) {
        int u = idx >> 6, k = idx & 63;
        sW3T[k*16 + u] = w3[idx];
    }

    float acc[2][4][4] = {};

    // ======== layer 1 (HMMA): K = 768, 12 chunks of 64 ========
    const int row = tid >> 1;
    const int half = tid & 1;
    for (int ch = 0; ch < 12; ++ch) {
        __syncthreads();
        // w1 chunk (hi/lo) -> sB
        {
            const uint32_t* src = ((const uint32_t*)g_w1p) + ch*4096;
            #pragma unroll
            for (int it = 0; it < 8; ++it) {
                int idx = tid + it*256;
                int n = idx >> 5, kk = idx & 31;
                sBh[n*AST + kk] = src[idx];
                sBl[n*AST + kk] = src[idx + 2048];
            }
        }
        // features for this chunk -> sA (hi/lo)
        {
            int seg = ch >> 1;
            int d0 = (ch & 1)*64 + half*32;
            int colp0 = half*16;
            const float* pA; const float* pB = nullptr; float inv = 1.f;
            int mode;
            if (seg == 0)      { pA = x + sXI[row]; mode = 0; }
            else if (seg == 1) { pA = x + sXJ[row]; mode = 0; }
            else if (seg == 2) { pA = x + sXI[row]; pB = x + sXJ[row]; mode = 1; }
            else {
                const float* c0 = g_cum + (seg - 3)*CUMSZ;
                pA = c0 + sCI[row]; pB = c0 + sCJ[row]; inv = sInv[row]; mode = 2;
            }
            #pragma unroll
            for (int q = 0; q < 8; ++q) {
                float4 a = *(const float4*)(pA + d0 + q*4);
                float f0, f1, f2, f3;
                if (mode == 0) { f0 = a.x; f1 = a.y; f2 = a.z; f3 = a.w; }
                else {
                    float4 bv = *(const float4*)(pB + d0 + q*4);
                    if (mode == 1) { f0 = a.x*bv.x; f1 = a.y*bv.y; f2 = a.z*bv.z; f3 = a.w*bv.w; }
                    else { f0 = (a.x-bv.x)*inv; f1 = (a.y-bv.y)*inv; f2 = (a.z-bv.z)*inv; f3 = (a.w-bv.w)*inv; }
                }
                uint32_t h0, l0, h1, l1;
                split2(f0, f1, h0, l0);
                split2(f2, f3, h1, l1);
                int o = row*AST + colp0 + q*2;
                sAh[o] = h0; sAh[o+1] = h1;
                sAl[o] = l0; sAl[o+1] = l1;
            }
        }
        __syncthreads();
        mma_block(acc, sAh, sAl, sBh, sBl, mbase, nbase, g, tg);
    }

    // ======== bias + gelu -> sHf (fp32, aliases sA region) ========
    __syncthreads();
    #pragma unroll
    for (int mi = 0; mi < 2; ++mi) {
        #pragma unroll
        for (int ni = 0; ni < 4; ++ni) {
            int col = nbase + ni*8 + tg*2;
            int r0 = mbase + mi*16 + g;
            sHf[r0*68 + col]       = gelu_f(acc[mi][ni][0] + sb1[col]);
            sHf[r0*68 + col + 1]   = gelu_f(acc[mi][ni][1] + sb1[col+1]);
            sHf[(r0+8)*68 + col]   = gelu_f(acc[mi][ni][2] + sb1[col]);
            sHf[(r0+8)*68 + col+1] = gelu_f(acc[mi][ni][3] + sb1[col+1]);
        }
    }
    __syncthreads();

    // ======== layers 2-3 (scalar fp32, exact) ========
    {
        const int row2 = tid >> 1;
        const int ob = (tid & 1)*8;
        float h2[64] = {};
        #pragma unroll 4
        for (int k = 0; k < 64; ++k) {
            float a = sHf[row2*68 + k];
            const float4* wp = (const float4*)&sW2T[k*64];
            #pragma unroll
            for (int uq = 0; uq < 16; ++uq) {
                float4 w = wp[uq];
                h2[uq*4+0] += a*w.x;
                h2[uq*4+1] += a*w.y;
                h2[uq*4+2] += a*w.z;
                h2[uq*4+3] += a*w.w;
            }
        }
        #pragma unroll
        for (int u = 0; u < 64; ++u) h2[u] = gelu_f(h2[u] + sb2[u]);

        float o8[8];
        #pragma unroll
        for (int o = 0; o < 8; ++o) o8[o] = sb3[ob + o];
        #pragma unroll 8
        for (int k = 0; k < 64; ++k) {
            float a = h2[k];
            const float4* wp = (const float4*)&sW3T[k*16 + ob];
            float4 w0 = wp[0], w1 = wp[1];
            o8[0] += a*w0.x; o8[1] += a*w0.y; o8[2] += a*w0.z; o8[3] += a*w0.w;
            o8[4] += a*w1.x; o8[5] += a*w1.y; o8[6] += a*w1.z; o8[7] += a*w1.w;
        }
        int base = sOut[row2];
        #pragma unroll
        for (int o = 0; o < 8; ++o)
            g_Spre[base + (ob + o)*262144] = o8[o];
    }
}

// ---------------- skip MLP (scalar, validated path) ----------------
__global__ __launch_bounds__(256) void skip_kernel(
    const float* __restrict__ x,
    const float* __restrict__ w1, const float* __restrict__ b1,
    const float* __restrict__ w2, const float* __restrict__ b2,
    const float* __restrict__ w3, const float* __restrict__ b3,
    float* __restrict__ outSkip)
{
    __shared__ float sAB[64*68];
    __shared__ float sH [64*68];
    __shared__ int   sXI[64], sXJ[64];
    __shared__ float sb1[64], sb2[64], sb3[16];

    const int tid = threadIdx.x;
    const int ty4 = (tid >> 4) * 4;
    const int tx4 = (tid & 15) * 4;

    if (tid < 64) {
        int r = blockIdx.x*64 + tid;
        if (r >= SKIP_ROWS) r = SKIP_ROWS - 1;
        int p = r >> 1, b = r & 1;
        sXI[tid] = p*256 + b*128;
        sXJ[tid] = (p+1)*256 + b*128;
        sb1[tid] = b1[tid];
        sb2[tid] = b2[tid];
        if (tid < 16) sb3[tid] = b3[tid];
    }
    __syncthreads();

    float acc[4][4] = {};
    for (int kc = 0; kc < 12; ++kc) {
        const int k0  = kc*32;
        const int seg = k0 >> 7;
        const int d0  = k0 & 127;
        if (kc) __syncthreads();
        #pragma unroll
        for (int e = 0; e < 8; ++e) {
            int idx = tid + e*256;
            int rw = idx >> 5, kk = idx & 31;
            int d = d0 + kk;
            float v;
            if (seg == 0)      v = x[sXI[rw] + d];
            else if (seg == 1) v = x[sXJ[rw] + d];
            else               v = x[sXI[rw] + d] * x[sXJ[rw] + d];
            sAB[kk*68 + rw] = v;
        }
        #pragma unroll
        for (int e = 0; e < 8; ++e) {
            int idx = tid + e*256;
            int col = idx >> 5, kk = idx & 31;
            sAB[(32+kk)*68 + col] = w1[col*384 + k0 + kk];
        }
        __syncthreads();
        #pragma unroll
        for (int kk = 0; kk < 32; ++kk) {
            float4 a  = *(const float4*)&sAB[kk*68 + ty4];
            float4 bv = *(const float4*)&sAB[(32+kk)*68 + tx4];
            acc[0][0] += a.x*bv.x; acc[0][1] += a.x*bv.y; acc[0][2] += a.x*bv.z; acc[0][3] += a.x*bv.w;
            acc[1][0] += a.y*bv.x; acc[1][1] += a.y*bv.y; acc[1][2] += a.y*bv.z; acc[1][3] += a.y*bv.w;
            acc[2][0] += a.z*bv.x; acc[2][1] += a.z*bv.y; acc[2][2] += a.z*bv.z; acc[2][3] += a.z*bv.w;
            acc[3][0] += a.w*bv.x; acc[3][1] += a.w*bv.y; acc[3][2] += a.w*bv.z; acc[3][3] += a.w*bv.w;
        }
    }
    __syncthreads();
    #pragma unroll
    for (int c = 0; c < 4; ++c) {
        float bias = sb1[tx4 + c];
        #pragma unroll
        for (int r = 0; r < 4; ++r)
            sH[(tx4 + c)*68 + ty4 + r] = gelu_f(acc[r][c] + bias);
    }
    #pragma unroll
    for (int e = 0; e < 16; ++e) {
        int idx = tid + e*256;
        int col = idx >> 6, kk = idx & 63;
        sAB[kk*68 + col] = w2[col*64 + kk];
    }
    __syncthreads();
    float acc2[4][4] = {};
    #pragma unroll
    for (int kk = 0; kk < 64; ++kk) {
        float4 a  = *(const float4*)&sH [kk*68 + ty4];
        float4 bv = *(const float4*)&sAB[kk*68 + tx4];
        acc2[0][0] += a.x*bv.x; acc2[0][1] += a.x*bv.y; acc2[0][2] += a.x*bv.z; acc2[0][3] += a.x*bv.w;
        acc2[1][0] += a.y*bv.x; acc2[1][1] += a.y*bv.y; acc2[1][2] += a.y*bv.z; acc2[1][3] += a.y*bv.w;
        acc2[2][0] += a.z*bv.x; acc2[2][1] += a.z*bv.y; acc2[2][2] += a.z*bv.z; acc2[2][3] += a.z*bv.w;
        acc2[3][0] += a.w*bv.x; acc2[3][1] += a.w*bv.y; acc2[3][2] += a.w*bv.z; acc2[3][3] += a.w*bv.w;
    }
    __syncthreads();
    #pragma unroll
    for (int c = 0; c < 4; ++c) {
        float bias = sb2[tx4 + c];
        #pragma unroll
        for (int r = 0; r < 4; ++r)
            sH[(tx4 + c)*68 + ty4 + r] = gelu_f(acc2[r][c] + bias);
    }
    #pragma unroll
    for (int e = 0; e < 4; ++e) {
        int idx = tid + e*256;
        int col = idx & 15, kk = idx >> 4;
        sAB[kk*16 + col] = w3[col*64 + kk];
    }
    __syncthreads();
    const int rw = tid >> 2;
    const int cg  = (tid & 3)*4;
    float o4[4] = {};
    #pragma unroll
    for (int kk = 0; kk < 64; ++kk) {
        float a   = sH[kk*68 + rw];
        float4 wv = *(const float4*)&sAB[kk*16 + cg];
        o4[0] += a*wv.x; o4[1] += a*wv.y; o4[2] += a*wv.z; o4[3] += a*wv.w;
    }
    int rg = blockIdx.x*64 + rw;
    if (rg < SKIP_ROWS) {
        #pragma unroll
        for (int c = 0; c < 4; ++c)
            outSkip[rg*16 + cg + c] = o4[c] + sb3[cg + c];
    }
}

// ---------------- conv1: 16 -> 48, 3x3, pad 2, + GELU ----------------
__global__ __launch_bounds__(256) void conv1_kernel(
    const float* __restrict__ cw1, const float* __restrict__ cb1)
{
    extern __shared__ float smem[];
    float* sIn = smem;                 // [16][18][67]
    float* sW  = smem + 16*18*67;      // [12][16][9]
    const int tid = threadIdx.x;
    const int b = blockIdx.z >> 2, gg = blockIdx.z & 3;
    const int by = blockIdx.y, bx = blockIdx.x;
    const int ty = tid >> 4, tx = tid & 15;

    for (int idx = tid; idx < 16*18*66; idx += 256) {
        int c  = idx / 1188;
        int rem = idx - c*1188;
        int sy = rem / 66, sx = rem - sy*66;
        int iy = by*16 + sy - 2;
        int ix = bx*64 + sx - 2;
        float v = 0.f;
        if (iy >= 0 && iy < 512 && ix >= 0 && ix < 512 && iy >= ix)
            v = g_Spre[((b*16 + c) << 18) + (iy << 9) + ix];
        sIn[(c*18 + sy)*67 + sx] = v;
    }
    for (int idx = tid; idx < 12*16*9; idx += 256)
        sW[idx] = cw1[gg*12*144 + idx];
    __syncthreads();

    float acc[12][4] = {};
    #pragma unroll 1
    for (int c = 0; c < 16; ++c) {
        #pragma unroll
        for (int ky = 0; ky < 3; ++ky) {
            const float* rp = &sIn[(c*18 + ty + ky)*67 + tx*4];
            float vv[6];
            #pragma unroll
            for (int m = 0; m < 6; ++m) vv[m] = rp[m];
            #pragma unroll
            for (int kx = 0; kx < 3; ++kx) {
                #pragma unroll
                for (int oc = 0; oc < 12; ++oc) {
                    float w = sW[(oc*16 + c)*9 + ky*3 + kx];
                    acc[oc][0] += w*vv[kx+0];
                    acc[oc][1] += w*vv[kx+1];
                    acc[oc][2] += w*vv[kx+2];
                    acc[oc][3] += w*vv[kx+3];
                }
            }
        }
    }
    int oy = by*16 + ty;
    int ox0 = bx*64 + tx*4;
    if (oy < 514) {
        #pragma unroll
        for (int oc = 0; oc < 12; ++oc) {
            int oco = gg*12 + oc;
            float bias = cb1[oco];
            long base = ((long)(b*48 + oco)*514 + oy)*516 + ox0;
            if (ox0 + 3 < 514) {
                *(float4*)&g_H1[base] = make_float4(
                    gelu_f(acc[oc][0] + bias), gelu_f(acc[oc][1] + bias),
                    gelu_f(acc[oc][2] + bias), gelu_f(acc[oc][3] + bias));
            } else {
                #pragma unroll
                for (int px = 0; px < 4; ++px)
                    if (ox0 + px < 514) g_H1[base + px] = gelu_f(acc[oc][px] + bias);
            }
        }
    }
}

// ---------------- conv2: 48 -> 16, 3x3 valid, + bias + length-scale + store ----------------
__global__ __launch_bounds__(256) void conv2_kernel(
    const float* __restrict__ cw2, const float* __restrict__ cb2,
    float* __restrict__ out)
{
    extern __shared__ float smem[];
    float* sIn = smem;                 // [12][18][67]
    float* sW  = smem + 12*18*67;      // [16][48][9]
    const int tid = threadIdx.x;
    const int b = blockIdx.z;
    const int by = blockIdx.y, bx = blockIdx.x;
    const int ty = tid >> 4, tx = tid & 15;

    for (int idx = tid; idx < 16*48*9; idx += 256) sW[idx] = cw2[idx];

    float acc[16][4] = {};
    for (int cc = 0; cc < 4; ++cc) {
        __syncthreads();
        for (int idx = tid; idx < 12*18*66; idx += 256) {
            int c  = idx / 1188;
            int rem = idx - c*1188;
            int sy = rem / 66, sx = rem - sy*66;
            sIn[(c*18 + sy)*67 + sx] =
                g_H1[((long)(b*48 + cc*12 + c)*514 + by*16 + sy)*516 + bx*64 + sx];
        }
        __syncthreads();
        #pragma unroll 1
        for (int c = 0; c < 12; ++c) {
            #pragma unroll
            for (int ky = 0; ky < 3; ++ky) {
                const float* rp = &sIn[(c*18 + ty + ky)*67 + tx*4];
                float vv[6];
                #pragma unroll
                for (int m = 0; m < 6; ++m) vv[m] = rp[m];
                #pragma unroll
                for (int kx = 0; kx < 3; ++kx) {
                    #pragma unroll
                    for (int oc = 0; oc < 16; ++oc) {
                        float w = sW[(oc*48 + cc*12 + c)*9 + ky*3 + kx];
                        acc[oc][0] += w*vv[kx+0];
                        acc[oc][1] += w*vv[kx+1];
                        acc[oc][2] += w*vv[kx+2];
                        acc[oc][3] += w*vv[kx+3];
                    }
                }
            }
        }
    }
    int oy = by*16 + ty;
    int ox0 = bx*64 + tx*4;
    float bias[16];
    #pragma unroll
    for (int oc = 0; oc < 16; ++oc) bias[oc] = cb2[oc];
    #pragma unroll
    for (int px = 0; px < 4; ++px) {
        int ox = ox0 + px;
        int ad = oy - ox; if (ad < 0) ad = -ad; if (ad < 1) ad = 1;
        float len = (float)ad;
        float o[16];
        #pragma unroll
        for (int oc = 0; oc < 16; ++oc) o[oc] = len*(acc[oc][px] + bias[oc]);
        float4* ob = (float4*)(out + ((long)(oy*512 + ox)*2 + b)*16);
        ob[0] = make_float4(o[0],  o[1],  o[2],  o[3]);
        ob[1] = make_float4(o[4],  o[5],  o[6],  o[7]);
        ob[2] = make_float4(o[8],  o[9],  o[10], o[11]);
        ob[3] = make_float4(o[12], o[13], o[14], o[15]);
    }
}

// ---------------- launch ----------------
extern "C" void kernel_launch(void* const* d_in, const int* in_sizes, int n_in,
                              void* d_out, int out_size)
{
    const float* x   = (const float*)d_in[0];
    const float* w1  = (const float*)d_in[1];
    const float* b1  = (const float*)d_in[2];
    const float* w2  = (const float*)d_in[3];
    const float* b2  = (const float*)d_in[4];
    const float* w3  = (const float*)d_in[5];
    const float* b3  = (const float*)d_in[6];
    const float* sw1 = (const float*)d_in[7];
    const float* sb1 = (const float*)d_in[8];
    const float* sw2 = (const float*)d_in[9];
    const float* sb2 = (const float*)d_in[10];
    const float* sw3 = (const float*)d_in[11];
    const float* sb3 = (const float*)d_in[12];
    const float* cw1 = (const float*)d_in[13];
    const float* cb1 = (const float*)d_in[14];
    const float* cw2 = (const float*)d_in[15];
    const float* cb2 = (const float*)d_in[16];
    float* out = (float*)d_out;

    const int c1_smem = (16*18*67 + 12*16*9)*4;
    const int c2_smem = (12*18*67 + 16*48*9)*4;
    const int mma_smem = MMA_SMEM_U32*4;
    static bool attr_done = false;
    if (!attr_done) {
        cudaFuncSetAttribute(conv1_kernel, cudaFuncAttributeMaxDynamicSharedMemorySize, c1_smem);
        cudaFuncSetAttribute(conv2_kernel, cudaFuncAttributeMaxDynamicSharedMemorySize, c2_smem);
        cudaFuncSetAttribute(pair_mma_kernel, cudaFuncAttributeMaxDynamicSharedMemorySize, mma_smem);
        attr_done = true;
    }

    prefix_kernel<<<1, 256>>>(x);
    prep_w_kernel<<<64, 256>>>(w1);
    pair_mma_kernel<<<PAIR_BLOCKS, 256, mma_smem>>>(x, b1, b2, b3, w2, w3);
    skip_kernel<<<(SKIP_ROWS + 63)/64, 256>>>(x, sw1, sb1, sw2, sb2, sw3, sb3, out + S_OUT_SZ);
    conv1_kernel<<<dim3(9, 33, 8), 256, c1_smem>>>(cw1, cb1);
    conv2_kernel<<<dim3(8, 32, 2), 256, c2_smem>>>(cw2, cb2, out);
}

// round 10
// speedup vs baseline: 2.1772x; 1.2634x over previous
#include <cuda_runtime.h>
#include <cuda_bf16.h>
#include <cstdint>
#include <math.h>

// ---------------- problem constants ----------------
#define NN   512
#define CUMSZ (513*256)           // [513][B][D]
#define SPRE_SZ (2*16*512*512)    // [B][O][512][512]
#define H1_SZ   (2*48*514*516)    // [B][CH][514][516]
#define S_OUT_SZ (512*512*2*16)
#define PAIR_ROWS 262656
#define PAIR_BLOCKS (PAIR_ROWS/128)   // 2052
#define SKIP_ROWS 1022
#define SKIP_BLOCKS 16
#define AST 36                       // A/B smem row stride in u32

__device__ float g_cum[3*CUMSZ];
__device__ float g_Spre[SPRE_SZ];
__device__ float g_H1[H1_SZ];
// prepped w1: bf16 hi/lo, [chunk][hl][n][k]
__device__ __align__(16) __nv_bfloat16 g_w1p[6*2*64*64];

__device__ __forceinline__ float gelu_f(float v) {
    return 0.5f*v*(1.0f + erff(v*0.70710678118654752440f));
}

__device__ __forceinline__ void split2(float v0, float v1, uint32_t& hi, uint32_t& lo) {
    __nv_bfloat16 h0 = __float2bfloat16(v0);
    __nv_bfloat16 h1 = __float2bfloat16(v1);
    float h0f = __uint_as_float(((uint32_t)__bfloat16_as_ushort(h0)) << 16);
    float h1f = __uint_as_float(((uint32_t)__bfloat16_as_ushort(h1)) << 16);
    __nv_bfloat16 l0 = __float2bfloat16(v0 - h0f);
    __nv_bfloat16 l1 = __float2bfloat16(v1 - h1f);
    hi = (uint32_t)__bfloat16_as_ushort(h0) | ((uint32_t)__bfloat16_as_ushort(h1) << 16);
    lo = (uint32_t)__bfloat16_as_ushort(l0) | ((uint32_t)__bfloat16_as_ushort(l1) << 16);
}

__device__ __forceinline__ void mma16816(float* d, const uint32_t* a, uint32_t b0, uint32_t b1) {
    asm volatile("mma.sync.aligned.m16n8k16.row.col.f32.bf16.bf16.f32 "
        "{%0,%1,%2,%3}, {%4,%5,%6,%7}, {%8,%9}, {%0,%1,%2,%3};"
        : "+f"(d[0]), "+f"(d[1]), "+f"(d[2]), "+f"(d[3])
        : "r"(a[0]), "r"(a[1]), "r"(a[2]), "r"(a[3]), "r"(b0), "r"(b1));
}

// 3-pass (Ah*Bh + Ah*Bl + Al*Bh) MMA over one K=64 chunk: 32x32 per warp
__device__ __forceinline__ void mma_block(
    float acc[2][4][4],
    const uint32_t* sAh, const uint32_t* sAl,
    const uint32_t* sBh, const uint32_t* sBl,
    int mbase, int nbase, int g, int tg)
{
    #pragma unroll
    for (int pass = 0; pass < 3; ++pass) {
        const uint32_t* A = (pass == 2) ? sAl : sAh;
        const uint32_t* B = (pass == 1) ? sBl : sBh;
        #pragma unroll
        for (int kt = 0; kt < 4; ++kt) {
            uint32_t af[2][4];
            #pragma unroll
            for (int mi = 0; mi < 2; ++mi) {
                int r0 = (mbase + mi*16 + g)*AST + kt*8 + tg;
                af[mi][0] = A[r0];
                af[mi][1] = A[r0 + 8*AST];
                af[mi][2] = A[r0 + 4];
                af[mi][3] = A[r0 + 8*AST + 4];
            }
            #pragma unroll
            for (int ni = 0; ni < 4; ++ni) {
                int rb = (nbase + ni*8 + g)*AST + kt*8 + tg;
                uint32_t b0 = B[rb], b1 = B[rb + 4];
                mma16816(acc[0][ni], af[0], b0, b1);
                mma16816(acc[1][ni], af[1], b0, b1);
            }
        }
    }
}

// ---------------- prefix sums of x, x^2, x^3 ----------------
__global__ void prefix_kernel(const float* __restrict__ x) {
    int t = threadIdx.x;
    float s1 = 0.f, s2 = 0.f, s3 = 0.f;
    g_cum[t] = 0.f; g_cum[CUMSZ + t] = 0.f; g_cum[2*CUMSZ + t] = 0.f;
    for (int n = 0; n < NN; ++n) {
        float v = x[n*256 + t];
        float v2 = v*v;
        s1 += v; s2 += v2; s3 += v2*v;
        int o = (n+1)*256 + t;
        g_cum[o] = s1; g_cum[CUMSZ + o] = s2; g_cum[2*CUMSZ + o] = s3;
    }
}

// ---------------- weight prep: w1 fp32 -> bf16 hi/lo ----------------
__global__ void prep_w_kernel(const float* __restrict__ w1) {
    int i0 = blockIdx.x*blockDim.x + threadIdx.x;
    int stride = gridDim.x*blockDim.x;
    for (int idx = i0; idx < 64*768; idx += stride) {
        int n = idx / 768, k = idx % 768;
        int ch = k >> 6, kk = k & 63;
        float v = w1[idx];
        __nv_bfloat16 h = __float2bfloat16(v);
        float hf = __uint_as_float(((uint32_t)__bfloat16_as_ushort(h)) << 16);
        __nv_bfloat16 l = __float2bfloat16(v - hf);
        g_w1p[((ch*2 + 0)*64 + n)*64 + kk] = h;
        g_w1p[((ch*2 + 1)*64 + n)*64 + kk] = l;
    }
}

// ---------------- skip MLP body (scalar, validated; runs on dynamic smem) ----------------
__device__ void skip_body(
    float* dsmf, int sblk,
    const float* __restrict__ x,
    const float* __restrict__ w1, const float* __restrict__ b1,
    const float* __restrict__ w2, const float* __restrict__ b2,
    const float* __restrict__ w3, const float* __restrict__ b3,
    float* __restrict__ outSkip)
{
    float* sAB = dsmf;               // 64*68
    float* sH  = dsmf + 64*68;       // 64*68
    int*   sXI = (int*)(dsmf + 2*64*68);
    int*   sXJ = sXI + 64;
    float* sb1 = (float*)(sXJ + 64);
    float* sb2 = sb1 + 64;
    float* sb3 = sb2 + 64;

    const int tid = threadIdx.x;
    const int ty4 = (tid >> 4) * 4;
    const int tx4 = (tid & 15) * 4;

    if (tid < 64) {
        int r = sblk*64 + tid;
        if (r >= SKIP_ROWS) r = SKIP_ROWS - 1;
        int p = r >> 1, b = r & 1;
        sXI[tid] = p*256 + b*128;
        sXJ[tid] = (p+1)*256 + b*128;
        sb1[tid] = b1[tid];
        sb2[tid] = b2[tid];
        if (tid < 16) sb3[tid] = b3[tid];
    }
    __syncthreads();

    float acc[4][4] = {};
    for (int kc = 0; kc < 12; ++kc) {
        const int k0  = kc*32;
        const int seg = k0 >> 7;
        const int d0  = k0 & 127;
        if (kc) __syncthreads();
        #pragma unroll
        for (int e = 0; e < 8; ++e) {
            int idx = tid + e*256;
            int rw = idx >> 5, kk = idx & 31;
            int d = d0 + kk;
            float v;
            if (seg == 0)      v = x[sXI[rw] + d];
            else if (seg == 1) v = x[sXJ[rw] + d];
            else               v = x[sXI[rw] + d] * x[sXJ[rw] + d];
            sAB[kk*68 + rw] = v;
        }
        #pragma unroll
        for (int e = 0; e < 8; ++e) {
            int idx = tid + e*256;
            int col = idx >> 5, kk = idx & 31;
            sAB[(32+kk)*68 + col] = w1[col*384 + k0 + kk];
        }
        __syncthreads();
        #pragma unroll
        for (int kk = 0; kk < 32; ++kk) {
            float4 a  = *(const float4*)&sAB[kk*68 + ty4];
            float4 bv = *(const float4*)&sAB[(32+kk)*68 + tx4];
            acc[0][0] += a.x*bv.x; acc[0][1] += a.x*bv.y; acc[0][2] += a.x*bv.z; acc[0][3] += a.x*bv.w;
            acc[1][0] += a.y*bv.x; acc[1][1] += a.y*bv.y; acc[1][2] += a.y*bv.z; acc[1][3] += a.y*bv.w;
            acc[2][0] += a.z*bv.x; acc[2][1] += a.z*bv.y; acc[2][2] += a.z*bv.z; acc[2][3] += a.z*bv.w;
            acc[3][0] += a.w*bv.x; acc[3][1] += a.w*bv.y; acc[3][2] += a.w*bv.z; acc[3][3] += a.w*bv.w;
        }
    }
    __syncthreads();
    #pragma unroll
    for (int c = 0; c < 4; ++c) {
        float bias = sb1[tx4 + c];
        #pragma unroll
        for (int r = 0; r < 4; ++r)
            sH[(tx4 + c)*68 + ty4 + r] = gelu_f(acc[r][c] + bias);
    }
    #pragma unroll
    for (int e = 0; e < 16; ++e) {
        int idx = tid + e*256;
        int col = idx >> 6, kk = idx & 63;
        sAB[kk*68 + col] = w2[col*64 + kk];
    }
    __syncthreads();
    float acc2[4][4] = {};
    #pragma unroll
    for (int kk = 0; kk < 64; ++kk) {
        float4 a  = *(const float4*)&sH [kk*68 + ty4];
        float4 bv = *(const float4*)&sAB[kk*68 + tx4];
        acc2[0][0] += a.x*bv.x; acc2[0][1] += a.x*bv.y; acc2[0][2] += a.x*bv.z; acc2[0][3] += a.x*bv.w;
        acc2[1][0] += a.y*bv.x; acc2[1][1] += a.y*bv.y; acc2[1][2] += a.y*bv.z; acc2[1][3] += a.y*bv.w;
        acc2[2][0] += a.z*bv.x; acc2[2][1] += a.z*bv.y; acc2[2][2] += a.z*bv.z; acc2[2][3] += a.z*bv.w;
        acc2[3][0] += a.w*bv.x; acc2[3][1] += a.w*bv.y; acc2[3][2] += a.w*bv.z; acc2[3][3] += a.w*bv.w;
    }
    __syncthreads();
    #pragma unroll
    for (int c = 0; c < 4; ++c) {
        float bias = sb2[tx4 + c];
        #pragma unroll
        for (int r = 0; r < 4; ++r)
            sH[(tx4 + c)*68 + ty4 + r] = gelu_f(acc2[r][c] + bias);
    }
    #pragma unroll
    for (int e = 0; e < 4; ++e) {
        int idx = tid + e*256;
        int col = idx & 15, kk = idx >> 4;
        sAB[kk*16 + col] = w3[col*64 + kk];
    }
    __syncthreads();
    const int rw = tid >> 2;
    const int cg  = (tid & 3)*4;
    float o4[4] = {};
    #pragma unroll
    for (int kk = 0; kk < 64; ++kk) {
        float a   = sH[kk*68 + rw];
        float4 wv = *(const float4*)&sAB[kk*16 + cg];
        o4[0] += a*wv.x; o4[1] += a*wv.y; o4[2] += a*wv.z; o4[3] += a*wv.w;
    }
    int rg = sblk*64 + rw;
    if (rg < SKIP_ROWS) {
        #pragma unroll
        for (int c = 0; c < 4; ++c)
            outSkip[rg*16 + cg + c] = o4[c] + sb3[cg + c];
    }
}

// ---------------- pair MLP: HMMA layer 1 + scalar fp32 layers 2-3 (+ skip tail) ----------------
// smem u32 offsets
#define O_AH 0
#define O_AL (O_AH + 128*AST)
#define O_BH (O_AL + 128*AST)
#define O_BL (O_BH + 64*AST)
#define O_XI (O_BL + 64*AST)
#define O_XJ (O_XI + 128)
#define O_CI (O_XJ + 128)
#define O_CJ (O_CI + 128)
#define O_OUT (O_CJ + 128)
#define O_INV (O_OUT + 128)
#define O_B1 (O_INV + 128)
#define O_B2 (O_B1 + 64)
#define O_B3 (O_B2 + 64)
#define O_W2T (O_B3 + 16)          // fp32 [k][64]  (4096)
#define O_W3T (O_W2T + 4096)       // fp32 [k][16]  (1024)
#define MMA_SMEM_U32 (O_W3T + 1024)

__global__ __launch_bounds__(256) void pair_mma_kernel(
    const float* __restrict__ x,
    const float* __restrict__ b1, const float* __restrict__ b2, const float* __restrict__ b3,
    const float* __restrict__ w2, const float* __restrict__ w3,
    const float* __restrict__ sw1, const float* __restrict__ sb1v,
    const float* __restrict__ sw2, const float* __restrict__ sb2v,
    const float* __restrict__ sw3, const float* __restrict__ sb3v,
    float* __restrict__ outSkip)
{
    extern __shared__ uint32_t sm[];

    if (blockIdx.x >= PAIR_BLOCKS) {    // uniform per block
        skip_body((float*)sm, blockIdx.x - PAIR_BLOCKS,
                  x, sw1, sb1v, sw2, sb2v, sw3, sb3v, outSkip);
        return;
    }

    uint32_t* sAh = sm + O_AH;
    uint32_t* sAl = sm + O_AL;
    uint32_t* sBh = sm + O_BH;
    uint32_t* sBl = sm + O_BL;
    float* sHf = (float*)(sm + O_AH);   // alias: fp32 H [128][68] after L1 (and h2 after L2)
    int*   sXI = (int*)(sm + O_XI);
    int*   sXJ = (int*)(sm + O_XJ);
    int*   sCI = (int*)(sm + O_CI);
    int*   sCJ = (int*)(sm + O_CJ);
    int*   sOut = (int*)(sm + O_OUT);
    float* sInv = (float*)(sm + O_INV);
    float* sb1 = (float*)(sm + O_B1);
    float* sb2 = (float*)(sm + O_B2);
    float* sb3 = (float*)(sm + O_B3);
    float* sW2T = (float*)(sm + O_W2T);
    float* sW3T = (float*)(sm + O_W3T);

    const int tid = threadIdx.x;
    const int wid = tid >> 5;
    const int lane = tid & 31;
    const int g = lane >> 2;
    const int tg = lane & 3;
    const int wm = wid & 3;
    const int wn = wid >> 2;
    const int mbase = wm*32;
    const int nbase = wn*32;

    if (tid < 128) {
        int r = blockIdx.x*128 + tid;
        int p = r >> 1, b = r & 1;
        int i = (int)((sqrt(8.0*(double)p + 1.0) - 1.0)*0.5);
        while ((i+1)*(i+2)/2 <= p) ++i;
        while (i*(i+1)/2 > p) --i;
        int j = p - i*(i+1)/2;
        sXI[tid] = i*256 + b*128;
        sXJ[tid] = j*256 + b*128;
        sCI[tid] = (i+1)*256 + b*128;
        sCJ[tid] = j*256 + b*128;
        sInv[tid] = 1.0f/(float)(i - j + 1);
        sOut[tid] = b*4194304 + i*512 + j;
    }
    if (tid < 64) { sb1[tid] = b1[tid]; sb2[tid] = b2[tid]; }
    if (tid >= 64 && tid < 80) sb3[tid - 64] = b3[tid - 64];
    // load w2/w3 transposed (fp32): sW2T[k*64+u] = w2[u*64+k]
    for (int idx = tid; idx < 4096; idx += 256) {
        int u = idx >> 6, k = idx & 63;
        sW2T[k*64 + u] = w2[idx];
    }
    for (int idx = tid; idx < 1024; idx += 256) {
        int u = idx >> 6, k = idx & 63;
        sW3T[k*16 + u] = w3[idx];
    }

    float acc[2][4][4] = {};

    // ======== layer 1 (HMMA): K = 768, 12 chunks of 64 ========
    const int row = tid >> 1;
    const int half = tid & 1;
    for (int ch = 0; ch < 12; ++ch) {
        __syncthreads();
        // w1 chunk (hi/lo) -> sB, vectorized uint4
        {
            const uint4* src = (const uint4*)(((const uint32_t*)g_w1p) + ch*4096);
            #pragma unroll
            for (int it = 0; it < 2; ++it) {
                int i4 = tid + it*256;            // 0..511
                int n = i4 >> 3, kw = (i4 & 7)*4;
                *(uint4*)&sBh[n*AST + kw] = src[i4];
                *(uint4*)&sBl[n*AST + kw] = src[i4 + 512];
            }
        }
        // features for this chunk -> sA (hi/lo)
        {
            int seg = ch >> 1;
            int d0 = (ch & 1)*64 + half*32;
            int colp0 = half*16;
            const float* pA; const float* pB = nullptr; float inv = 1.f;
            int mode;
            if (seg == 0)      { pA = x + sXI[row]; mode = 0; }
            else if (seg == 1) { pA = x + sXJ[row]; mode = 0; }
            else if (seg == 2) { pA = x + sXI[row]; pB = x + sXJ[row]; mode = 1; }
            else {
                const float* c0 = g_cum + (seg - 3)*CUMSZ;
                pA = c0 + sCI[row]; pB = c0 + sCJ[row]; inv = sInv[row]; mode = 2;
            }
            #pragma unroll
            for (int q = 0; q < 8; ++q) {
                float4 a = *(const float4*)(pA + d0 + q*4);
                float f0, f1, f2, f3;
                if (mode == 0) { f0 = a.x; f1 = a.y; f2 = a.z; f3 = a.w; }
                else {
                    float4 bv = *(const float4*)(pB + d0 + q*4);
                    if (mode == 1) { f0 = a.x*bv.x; f1 = a.y*bv.y; f2 = a.z*bv.z; f3 = a.w*bv.w; }
                    else { f0 = (a.x-bv.x)*inv; f1 = (a.y-bv.y)*inv; f2 = (a.z-bv.z)*inv; f3 = (a.w-bv.w)*inv; }
                }
                uint32_t h0, l0, h1, l1;
                split2(f0, f1, h0, l0);
                split2(f2, f3, h1, l1);
                int o = row*AST + colp0 + q*2;
                sAh[o] = h0; sAh[o+1] = h1;
                sAl[o] = l0; sAl[o+1] = l1;
            }
        }
        __syncthreads();
        mma_block(acc, sAh, sAl, sBh, sBl, mbase, nbase, g, tg);
    }

    // ======== bias + gelu -> sHf (fp32, aliases sA region) ========
    __syncthreads();
    #pragma unroll
    for (int mi = 0; mi < 2; ++mi) {
        #pragma unroll
        for (int ni = 0; ni < 4; ++ni) {
            int col = nbase + ni*8 + tg*2;
            int r0 = mbase + mi*16 + g;
            sHf[r0*68 + col]       = gelu_f(acc[mi][ni][0] + sb1[col]);
            sHf[r0*68 + col + 1]   = gelu_f(acc[mi][ni][1] + sb1[col+1]);
            sHf[(r0+8)*68 + col]   = gelu_f(acc[mi][ni][2] + sb1[col]);
            sHf[(r0+8)*68 + col+1] = gelu_f(acc[mi][ni][3] + sb1[col+1]);
        }
    }
    __syncthreads();

    // ======== layer 2 (scalar fp32, split across row-pair threads) ========
    {
        const int row2 = tid >> 1;
        const int ub = half*32;          // this thread's 32 units
        float h2[32] = {};
        #pragma unroll 4
        for (int k = 0; k < 64; ++k) {
            float a = sHf[row2*68 + k];
            const float4* wp = (const float4*)&sW2T[k*64 + ub];
            #pragma unroll
            for (int uq = 0; uq < 8; ++uq) {
                float4 w = wp[uq];
                h2[uq*4+0] += a*w.x;
                h2[uq*4+1] += a*w.y;
                h2[uq*4+2] += a*w.z;
                h2[uq*4+3] += a*w.w;
            }
        }
        #pragma unroll
        for (int u = 0; u < 32; ++u) h2[u] = gelu_f(h2[u] + sb2[ub + u]);
        __syncthreads();                 // all L2 reads of sHf done
        #pragma unroll
        for (int u = 0; u < 32; ++u) sHf[row2*68 + ub + u] = h2[u];
        __syncthreads();                 // h2 visible to partner thread

        // ======== layer 3 (scalar fp32) ========
        const int ob = half*8;
        float o8[8];
        #pragma unroll
        for (int o = 0; o < 8; ++o) o8[o] = sb3[ob + o];
        #pragma unroll 8
        for (int k = 0; k < 64; ++k) {
            float a = sHf[row2*68 + k];
            const float4* wp = (const float4*)&sW3T[k*16 + ob];
            float4 w0 = wp[0], w1 = wp[1];
            o8[0] += a*w0.x; o8[1] += a*w0.y; o8[2] += a*w0.z; o8[3] += a*w0.w;
            o8[4] += a*w1.x; o8[5] += a*w1.y; o8[6] += a*w1.z; o8[7] += a*w1.w;
        }
        int base = sOut[row2];
        #pragma unroll
        for (int o = 0; o < 8; ++o)
            g_Spre[base + (ob + o)*262144] = o8[o];
    }
}

// ---------------- conv1: 16 -> 48, 3x3, pad 2, + GELU (2 px/thread) ----------------
// grid (17, 33, 8): z = b*4 + g (12 oc per group). Tile 16y x 32x.
__global__ __launch_bounds__(256) void conv1_kernel(
    const float* __restrict__ cw1, const float* __restrict__ cb1)
{
    extern __shared__ float smem[];
    float* sIn = smem;                 // [16][18][35]
    float* sW  = smem + 16*18*35;      // [12][16][9]
    const int tid = threadIdx.x;
    const int b = blockIdx.z >> 2, gg = blockIdx.z & 3;
    const int by = blockIdx.y, bx = blockIdx.x;
    const int ty = tid >> 4, tx = tid & 15;

    for (int idx = tid; idx < 16*18*34; idx += 256) {
        int c  = idx / 612;
        int rem = idx - c*612;
        int sy = rem / 34, sx = rem - sy*34;
        int iy = by*16 + sy - 2;
        int ix = bx*32 + sx - 2;
        float v = 0.f;
        if (iy >= 0 && iy < 512 && ix >= 0 && ix < 512 && iy >= ix)
            v = g_Spre[((b*16 + c) << 18) + (iy << 9) + ix];
        sIn[(c*18 + sy)*35 + sx] = v;
    }
    for (int idx = tid; idx < 12*16*9; idx += 256)
        sW[idx] = cw1[gg*12*144 + idx];
    __syncthreads();

    float acc[12][2] = {};
    #pragma unroll 1
    for (int c = 0; c < 16; ++c) {
        #pragma unroll
        for (int ky = 0; ky < 3; ++ky) {
            const float* rp = &sIn[(c*18 + ty + ky)*35 + tx*2];
            float vv[4];
            #pragma unroll
            for (int m = 0; m < 4; ++m) vv[m] = rp[m];
            #pragma unroll
            for (int kx = 0; kx < 3; ++kx) {
                #pragma unroll
                for (int oc = 0; oc < 12; ++oc) {
                    float w = sW[(oc*16 + c)*9 + ky*3 + kx];
                    acc[oc][0] += w*vv[kx+0];
                    acc[oc][1] += w*vv[kx+1];
                }
            }
        }
    }
    int oy = by*16 + ty;
    int ox0 = bx*32 + tx*2;
    if (oy < 514 && ox0 < 514) {
        #pragma unroll
        for (int oc = 0; oc < 12; ++oc) {
            int oco = gg*12 + oc;
            float bias = cb1[oco];
            long base = ((long)(b*48 + oco)*514 + oy)*516 + ox0;
            *(float2*)&g_H1[base] = make_float2(
                gelu_f(acc[oc][0] + bias), gelu_f(acc[oc][1] + bias));
        }
    }
}

// ---------------- conv2: 48 -> 16, 3x3 valid, + bias + length-scale + store (2 px/thread) ----------------
// grid (16, 32, 2): z = b. Tile 16y x 32x of 512x512.
__global__ __launch_bounds__(256) void conv2_kernel(
    const float* __restrict__ cw2, const float* __restrict__ cb2,
    float* __restrict__ out)
{
    extern __shared__ float smem[];
    float* sIn = smem;                 // [12][18][35]
    float* sW  = smem + 12*18*35;      // [16][48][9]
    const int tid = threadIdx.x;
    const int b = blockIdx.z;
    const int by = blockIdx.y, bx = blockIdx.x;
    const int ty = tid >> 4, tx = tid & 15;

    for (int idx = tid; idx < 16*48*9; idx += 256) sW[idx] = cw2[idx];

    float acc[16][2] = {};
    for (int cc = 0; cc < 4; ++cc) {
        __syncthreads();
        for (int idx = tid; idx < 12*18*34; idx += 256) {
            int c  = idx / 612;
            int rem = idx - c*612;
            int sy = rem / 34, sx = rem - sy*34;
            sIn[(c*18 + sy)*35 + sx] =
                g_H1[((long)(b*48 + cc*12 + c)*514 + by*16 + sy)*516 + bx*32 + sx];
        }
        __syncthreads();
        #pragma unroll 1
        for (int c = 0; c < 12; ++c) {
            #pragma unroll
            for (int ky = 0; ky < 3; ++ky) {
                const float* rp = &sIn[(c*18 + ty + ky)*35 + tx*2];
                float vv[4];
                #pragma unroll
                for (int m = 0; m < 4; ++m) vv[m] = rp[m];
                #pragma unroll
                for (int kx = 0; kx < 3; ++kx) {
                    #pragma unroll
                    for (int oc = 0; oc < 16; ++oc) {
                        float w = sW[(oc*48 + cc*12 + c)*9 + ky*3 + kx];
                        acc[oc][0] += w*vv[kx+0];
                        acc[oc][1] += w*vv[kx+1];
                    }
                }
            }
        }
    }
    int oy = by*16 + ty;
    int ox0 = bx*32 + tx*2;
    float bias[16];
    #pragma unroll
    for (int oc = 0; oc < 16; ++oc) bias[oc] = cb2[oc];
    #pragma unroll
    for (int px = 0; px < 2; ++px) {
        int ox = ox0 + px;
        int ad = oy - ox; if (ad < 0) ad = -ad; if (ad < 1) ad = 1;
        float len = (float)ad;
        float o[16];
        #pragma unroll
        for (int oc = 0; oc < 16; ++oc) o[oc] = len*(acc[oc][px] + bias[oc]);
        float4* ob = (float4*)(out + ((long)(oy*512 + ox)*2 + b)*16);
        ob[0] = make_float4(o[0],  o[1],  o[2],  o[3]);
        ob[1] = make_float4(o[4],  o[5],  o[6],  o[7]);
        ob[2] = make_float4(o[8],  o[9],  o[10], o[11]);
        ob[3] = make_float4(o[12], o[13], o[14], o[15]);
    }
}

// ---------------- launch ----------------
extern "C" void kernel_launch(void* const* d_in, const int* in_sizes, int n_in,
                              void* d_out, int out_size)
{
    const float* x   = (const float*)d_in[0];
    const float* w1  = (const float*)d_in[1];
    const float* b1  = (const float*)d_in[2];
    const float* w2  = (const float*)d_in[3];
    const float* b2  = (const float*)d_in[4];
    const float* w3  = (const float*)d_in[5];
    const float* b3  = (const float*)d_in[6];
    const float* sw1 = (const float*)d_in[7];
    const float* sb1 = (const float*)d_in[8];
    const float* sw2 = (const float*)d_in[9];
    const float* sb2 = (const float*)d_in[10];
    const float* sw3 = (const float*)d_in[11];
    const float* sb3 = (const float*)d_in[12];
    const float* cw1 = (const float*)d_in[13];
    const float* cb1 = (const float*)d_in[14];
    const float* cw2 = (const float*)d_in[15];
    const float* cb2 = (const float*)d_in[16];
    float* out = (float*)d_out;

    const int c1_smem = (16*18*35 + 12*16*9)*4;
    const int c2_smem = (12*18*35 + 16*48*9)*4;
    const int mma_smem = MMA_SMEM_U32*4;
    static bool attr_done = false;
    if (!attr_done) {
        cudaFuncSetAttribute(conv1_kernel, cudaFuncAttributeMaxDynamicSharedMemorySize, c1_smem);
        cudaFuncSetAttribute(conv2_kernel, cudaFuncAttributeMaxDynamicSharedMemorySize, c2_smem);
        cudaFuncSetAttribute(pair_mma_kernel, cudaFuncAttributeMaxDynamicSharedMemorySize, mma_smem);
        attr_done = true;
    }

    prefix_kernel<<<1, 256>>>(x);
    prep_w_kernel<<<64, 256>>>(w1);
    pair_mma_kernel<<<PAIR_BLOCKS + SKIP_BLOCKS, 256, mma_smem>>>(
        x, b1, b2, b3, w2, w3, sw1, sb1, sw2, sb2, sw3, sb3, out + S_OUT_SZ);
    conv1_kernel<<<dim3(17, 33, 8), 256, c1_smem>>>(cw1, cb1);
    conv2_kernel<<<dim3(16, 32, 2), 256, c2_smem>>>(cw2, cb2, out);
}

// round 13
// speedup vs baseline: 2.6641x; 1.2237x over previous
#include <cuda_runtime.h>
#include <cuda_bf16.h>
#include <cstdint>
#include <math.h>

// ---------------- problem constants ----------------
#define NN   512
#define CUMSZ (513*256)           // [513][B][D]
#define SPRE_SZ (2*16*512*512)    // [B][O][512][512]
#define H1_SZ   (2*48*514*516)    // [B][CH][514][516]
#define S_OUT_SZ (512*512*2*16)
#define PAIR_ROWS 262656
#define PAIR_BLOCKS (PAIR_ROWS/128)   // 2052
#define SKIP_ROWS 1022
#define SKIP_BLOCKS 16
#define AST 36                       // A/B smem row stride in u32

__device__ float g_cum[3*CUMSZ];
__device__ float g_Spre[SPRE_SZ];
__device__ float g_H1[H1_SZ];
__device__ float g_K2[16];
// prepped w1: bf16 hi/lo, [chunk][hl][n][k]
__device__ __align__(16) __nv_bfloat16 g_w1p[6*2*64*64];

__device__ __forceinline__ float gelu_f(float v) {
    return 0.5f*v*(1.0f + erff(v*0.70710678118654752440f));
}

__device__ __forceinline__ uint32_t smem_u32(const void* p) {
    uint32_t a;
    asm("{ .reg .u64 t; cvta.to.shared.u64 t, %1; cvt.u32.u64 %0, t; }" : "=r"(a) : "l"(p));
    return a;
}

__device__ __forceinline__ void split2(float v0, float v1, uint32_t& hi, uint32_t& lo) {
    __nv_bfloat16 h0 = __float2bfloat16(v0);
    __nv_bfloat16 h1 = __float2bfloat16(v1);
    float h0f = __uint_as_float(((uint32_t)__bfloat16_as_ushort(h0)) << 16);
    float h1f = __uint_as_float(((uint32_t)__bfloat16_as_ushort(h1)) << 16);
    __nv_bfloat16 l0 = __float2bfloat16(v0 - h0f);
    __nv_bfloat16 l1 = __float2bfloat16(v1 - h1f);
    hi = (uint32_t)__bfloat16_as_ushort(h0) | ((uint32_t)__bfloat16_as_ushort(h1) << 16);
    lo = (uint32_t)__bfloat16_as_ushort(l0) | ((uint32_t)__bfloat16_as_ushort(l1) << 16);
}

__device__ __forceinline__ void mma16816(float* d, const uint32_t* a, uint32_t b0, uint32_t b1) {
    asm volatile("mma.sync.aligned.m16n8k16.row.col.f32.bf16.bf16.f32 "
        "{%0,%1,%2,%3}, {%4,%5,%6,%7}, {%8,%9}, {%0,%1,%2,%3};"
        : "+f"(d[0]), "+f"(d[1]), "+f"(d[2]), "+f"(d[3])
        : "r"(a[0]), "r"(a[1]), "r"(a[2]), "r"(a[3]), "r"(b0), "r"(b1));
}

__device__ __forceinline__ void ldmx4(uint32_t* r, uint32_t addr) {
    asm volatile("ldmatrix.sync.aligned.m8n8.x4.shared.b16 {%0,%1,%2,%3}, [%4];"
        : "=r"(r[0]), "=r"(r[1]), "=r"(r[2]), "=r"(r[3]) : "r"(addr));
}

// ---------------- prefix sums of x, x^2, x^3 ----------------
__global__ void prefix_kernel(const float* __restrict__ x) {
    int t = threadIdx.x;
    float s1 = 0.f, s2 = 0.f, s3 = 0.f;
    g_cum[t] = 0.f; g_cum[CUMSZ + t] = 0.f; g_cum[2*CUMSZ + t] = 0.f;
    for (int n = 0; n < NN; ++n) {
        float v = x[n*256 + t];
        float v2 = v*v;
        s1 += v; s2 += v2; s3 += v2*v;
        int o = (n+1)*256 + t;
        g_cum[o] = s1; g_cum[CUMSZ + o] = s2; g_cum[2*CUMSZ + o] = s3;
    }
}

// ---------------- weight prep: w1 fp32 -> bf16 hi/lo; conv2 const K2 ----------------
__global__ void prep_w_kernel(const float* __restrict__ w1,
                              const float* __restrict__ cw2,
                              const float* __restrict__ cb1,
                              const float* __restrict__ cb2) {
    int i0 = blockIdx.x*blockDim.x + threadIdx.x;
    int stride = gridDim.x*blockDim.x;
    for (int idx = i0; idx < 64*768; idx += stride) {
        int n = idx / 768, k = idx % 768;
        int ch = k >> 6, kk = k & 63;
        float v = w1[idx];
        __nv_bfloat16 h = __float2bfloat16(v);
        float hf = __uint_as_float(((uint32_t)__bfloat16_as_ushort(h)) << 16);
        __nv_bfloat16 l = __float2bfloat16(v - hf);
        g_w1p[((ch*2 + 0)*64 + n)*64 + kk] = h;
        g_w1p[((ch*2 + 1)*64 + n)*64 + kk] = l;
    }
    if (blockIdx.x == 0 && threadIdx.x < 16) {
        int oc = threadIdx.x;
        float s = cb2[oc];
        for (int c = 0; c < 48; ++c) {
            float g = gelu_f(cb1[c]);
            float ws = 0.f;
            #pragma unroll
            for (int k = 0; k < 9; ++k) ws += cw2[(oc*48 + c)*9 + k];
            s += g*ws;
        }
        g_K2[oc] = s;
    }
}

// ---------------- skip MLP body (scalar, validated; runs on dynamic smem) ----------------
__device__ void skip_body(
    float* dsmf, int sblk,
    const float* __restrict__ x,
    const float* __restrict__ w1, const float* __restrict__ b1,
    const float* __restrict__ w2, const float* __restrict__ b2,
    const float* __restrict__ w3, const float* __restrict__ b3,
    float* __restrict__ outSkip)
{
    float* sAB = dsmf;               // 64*68
    float* sH  = dsmf + 64*68;       // 64*68
    int*   sXI = (int*)(dsmf + 2*64*68);
    int*   sXJ = sXI + 64;
    float* sb1 = (float*)(sXJ + 64);
    float* sb2 = sb1 + 64;
    float* sb3 = sb2 + 64;

    const int tid = threadIdx.x;
    const int ty4 = (tid >> 4) * 4;
    const int tx4 = (tid & 15) * 4;

    if (tid < 64) {
        int r = sblk*64 + tid;
        if (r >= SKIP_ROWS) r = SKIP_ROWS - 1;
        int p = r >> 1, b = r & 1;
        sXI[tid] = p*256 + b*128;
        sXJ[tid] = (p+1)*256 + b*128;
        sb1[tid] = b1[tid];
        sb2[tid] = b2[tid];
        if (tid < 16) sb3[tid] = b3[tid];
    }
    __syncthreads();

    float acc[4][4] = {};
    for (int kc = 0; kc < 12; ++kc) {
        const int k0  = kc*32;
        const int seg = k0 >> 7;
        const int d0  = k0 & 127;
        if (kc) __syncthreads();
        #pragma unroll
        for (int e = 0; e < 8; ++e) {
            int idx = tid + e*256;
            int rw = idx >> 5, kk = idx & 31;
            int d = d0 + kk;
            float v;
            if (seg == 0)      v = x[sXI[rw] + d];
            else if (seg == 1) v = x[sXJ[rw] + d];
            else               v = x[sXI[rw] + d] * x[sXJ[rw] + d];
            sAB[kk*68 + rw] = v;
        }
        #pragma unroll
        for (int e = 0; e < 8; ++e) {
            int idx = tid + e*256;
            int col = idx >> 5, kk = idx & 31;
            sAB[(32+kk)*68 + col] = w1[col*384 + k0 + kk];
        }
        __syncthreads();
        #pragma unroll
        for (int kk = 0; kk < 32; ++kk) {
            float4 a  = *(const float4*)&sAB[kk*68 + ty4];
            float4 bv = *(const float4*)&sAB[(32+kk)*68 + tx4];
            acc[0][0] += a.x*bv.x; acc[0][1] += a.x*bv.y; acc[0][2] += a.x*bv.z; acc[0][3] += a.x*bv.w;
            acc[1][0] += a.y*bv.x; acc[1][1] += a.y*bv.y; acc[1][2] += a.y*bv.z; acc[1][3] += a.y*bv.w;
            acc[2][0] += a.z*bv.x; acc[2][1] += a.z*bv.y; acc[2][2] += a.z*bv.z; acc[2][3] += a.z*bv.w;
            acc[3][0] += a.w*bv.x; acc[3][1] += a.w*bv.y; acc[3][2] += a.w*bv.z; acc[3][3] += a.w*bv.w;
        }
    }
    __syncthreads();
    #pragma unroll
    for (int c = 0; c < 4; ++c) {
        float bias = sb1[tx4 + c];
        #pragma unroll
        for (int r = 0; r < 4; ++r)
            sH[(tx4 + c)*68 + ty4 + r] = gelu_f(acc[r][c] + bias);
    }
    #pragma unroll
    for (int e = 0; e < 16; ++e) {
        int idx = tid + e*256;
        int col = idx >> 6, kk = idx & 63;
        sAB[kk*68 + col] = w2[col*64 + kk];
    }
    __syncthreads();
    float acc2[4][4] = {};
    #pragma unroll
    for (int kk = 0; kk < 64; ++kk) {
        float4 a  = *(const float4*)&sH [kk*68 + ty4];
        float4 bv = *(const float4*)&sAB[kk*68 + tx4];
        acc2[0][0] += a.x*bv.x; acc2[0][1] += a.x*bv.y; acc2[0][2] += a.x*bv.z; acc2[0][3] += a.x*bv.w;
        acc2[1][0] += a.y*bv.x; acc2[1][1] += a.y*bv.y; acc2[1][2] += a.y*bv.z; acc2[1][3] += a.y*bv.w;
        acc2[2][0] += a.z*bv.x; acc2[2][1] += a.z*bv.y; acc2[2][2] += a.z*bv.z; acc2[2][3] += a.z*bv.w;
        acc2[3][0] += a.w*bv.x; acc2[3][1] += a.w*bv.y; acc2[3][2] += a.w*bv.z; acc2[3][3] += a.w*bv.w;
    }
    __syncthreads();
    #pragma unroll
    for (int c = 0; c < 4; ++c) {
        float bias = sb2[tx4 + c];
        #pragma unroll
        for (int r = 0; r < 4; ++r)
            sH[(tx4 + c)*68 + ty4 + r] = gelu_f(acc2[r][c] + bias);
    }
    #pragma unroll
    for (int e = 0; e < 4; ++e) {
        int idx = tid + e*256;
        int col = idx & 15, kk = idx >> 4;
        sAB[kk*16 + col] = w3[col*64 + kk];
    }
    __syncthreads();
    const int rw = tid >> 2;
    const int cg  = (tid & 3)*4;
    float o4[4] = {};
    #pragma unroll
    for (int kk = 0; kk < 64; ++kk) {
        float a   = sH[kk*68 + rw];
        float4 wv = *(const float4*)&sAB[kk*16 + cg];
        o4[0] += a*wv.x; o4[1] += a*wv.y; o4[2] += a*wv.z; o4[3] += a*wv.w;
    }
    int rg = sblk*64 + rw;
    if (rg < SKIP_ROWS) {
        #pragma unroll
        for (int c = 0; c < 4; ++c)
            outSkip[rg*16 + cg + c] = o4[c] + sb3[cg + c];
    }
}

// ---------------- pair MLP: HMMA layer 1 (ldmatrix) + scalar fp32 layers 2-3 (+ skip tail) ----------------
// smem u32 offsets
#define O_AH 0
#define O_AL (O_AH + 128*AST)
#define O_BH (O_AL + 128*AST)
#define O_BL (O_BH + 64*AST)
#define O_XI (O_BL + 64*AST)
#define O_XJ (O_XI + 128)
#define O_CI (O_XJ + 128)
#define O_CJ (O_CI + 128)
#define O_OUT (O_CJ + 128)
#define O_INV (O_OUT + 128)
#define O_B1 (O_INV + 128)
#define O_B2 (O_B1 + 64)
#define O_B3 (O_B2 + 64)
#define O_W2T (O_B3 + 16)          // fp32 [k][64]  (4096)
#define O_W3T (O_W2T + 4096)       // fp32 [k][16]  (1024)
#define MMA_SMEM_U32 (O_W3T + 1024)

__global__ __launch_bounds__(256) void pair_mma_kernel(
    const float* __restrict__ x,
    const float* __restrict__ b1, const float* __restrict__ b2, const float* __restrict__ b3,
    const float* __restrict__ w2, const float* __restrict__ w3,
    const float* __restrict__ sw1, const float* __restrict__ sb1v,
    const float* __restrict__ sw2, const float* __restrict__ sb2v,
    const float* __restrict__ sw3, const float* __restrict__ sb3v,
    float* __restrict__ outSkip)
{
    extern __shared__ uint32_t sm[];

    if (blockIdx.x >= PAIR_BLOCKS) {    // uniform per block
        skip_body((float*)sm, blockIdx.x - PAIR_BLOCKS,
                  x, sw1, sb1v, sw2, sb2v, sw3, sb3v, outSkip);
        return;
    }

    uint32_t* sAh = sm + O_AH;
    uint32_t* sAl = sm + O_AL;
    uint32_t* sBh = sm + O_BH;
    uint32_t* sBl = sm + O_BL;
    float* sHf = (float*)(sm + O_AH);   // alias: fp32 H [128][68] after L1 (and h2 after L2)
    int*   sXI = (int*)(sm + O_XI);
    int*   sXJ = (int*)(sm + O_XJ);
    int*   sCI = (int*)(sm + O_CI);
    int*   sCJ = (int*)(sm + O_CJ);
    int*   sOut = (int*)(sm + O_OUT);
    float* sInv = (float*)(sm + O_INV);
    float* sb1 = (float*)(sm + O_B1);
    float* sb2 = (float*)(sm + O_B2);
    float* sb3 = (float*)(sm + O_B3);
    float* sW2T = (float*)(sm + O_W2T);
    float* sW3T = (float*)(sm + O_W3T);

    const int tid = threadIdx.x;
    const int wid = tid >> 5;
    const int lane = tid & 31;
    const int g = lane >> 2;
    const int tg = lane & 3;
    const int wm = wid & 3;
    const int wn = wid >> 2;
    const int mbase = wm*32;
    const int nbase = wn*32;

    if (tid < 128) {
        int r = blockIdx.x*128 + tid;
        int p = r >> 1, b = r & 1;
        int i = (int)((sqrt(8.0*(double)p + 1.0) - 1.0)*0.5);
        while ((i+1)*(i+2)/2 <= p) ++i;
        while (i*(i+1)/2 > p) --i;
        int j = p - i*(i+1)/2;
        sXI[tid] = i*256 + b*128;
        sXJ[tid] = j*256 + b*128;
        sCI[tid] = (i+1)*256 + b*128;
        sCJ[tid] = j*256 + b*128;
        sInv[tid] = 1.0f/(float)(i - j + 1);
        sOut[tid] = b*4194304 + i*512 + j;
    }
    if (tid < 64) { sb1[tid] = b1[tid]; sb2[tid] = b2[tid]; }
    if (tid >= 64 && tid < 80) sb3[tid - 64] = b3[tid - 64];
    // load w2/w3 transposed (fp32): sW2T[k*64+u] = w2[u*64+k]
    for (int idx = tid; idx < 4096; idx += 256) {
        int u = idx >> 6, k = idx & 63;
        sW2T[k*64 + u] = w2[idx];
    }
    for (int idx = tid; idx < 1024; idx += 256) {
        int u = idx >> 6, k = idx & 63;
        sW3T[k*16 + u] = w3[idx];
    }

    // ldmatrix lane base addresses (bytes)
    const uint32_t smb = smem_u32(sm);
    const int wi8 = lane & 7, quad = lane >> 3;
    const uint32_t laneoff = (uint32_t)(((wi8 + (quad & 1)*8)*AST + (quad >> 1)*4) * 4);
    const uint32_t aAh0 = smb + (uint32_t)(O_AH + mbase*AST)*4 + laneoff;
    const uint32_t aAh1 = aAh0 + 16*AST*4;
    const uint32_t aAl0 = aAh0 + (uint32_t)(O_AL - O_AH)*4;
    const uint32_t aAl1 = aAl0 + 16*AST*4;
    const uint32_t aBh0 = smb + (uint32_t)(O_BH + nbase*AST)*4 + laneoff;
    const uint32_t aBh1 = aBh0 + 16*AST*4;
    const uint32_t aBl0 = aBh0 + (uint32_t)(O_BL - O_BH)*4;
    const uint32_t aBl1 = aBl0 + 16*AST*4;

    float acc[2][4][4] = {};

    // ======== layer 1 (HMMA + ldmatrix): K = 768, 12 chunks of 64 ========
    const int row = tid >> 1;
    const int half = tid & 1;
    for (int ch = 0; ch < 12; ++ch) {
        __syncthreads();
        // w1 chunk (hi/lo) -> sB, vectorized uint4
        {
            const uint4* src = (const uint4*)(((const uint32_t*)g_w1p) + ch*4096);
            #pragma unroll
            for (int it = 0; it < 2; ++it) {
                int i4 = tid + it*256;            // 0..511
                int n = i4 >> 3, kw = (i4 & 7)*4;
                *(uint4*)&sBh[n*AST + kw] = src[i4];
                *(uint4*)&sBl[n*AST + kw] = src[i4 + 512];
            }
        }
        // features for this chunk -> sA (hi/lo)
        {
            int seg = ch >> 1;
            int d0 = (ch & 1)*64 + half*32;
            int colp0 = half*16;
            const float* pA; const float* pB = nullptr; float inv = 1.f;
            int mode;
            if (seg == 0)      { pA = x + sXI[row]; mode = 0; }
            else if (seg == 1) { pA = x + sXJ[row]; mode = 0; }
            else if (seg == 2) { pA = x + sXI[row]; pB = x + sXJ[row]; mode = 1; }
            else {
                const float* c0 = g_cum + (seg - 3)*CUMSZ;
                pA = c0 + sCI[row]; pB = c0 + sCJ[row]; inv = sInv[row]; mode = 2;
            }
            #pragma unroll
            for (int q = 0; q < 8; ++q) {
                float4 a = *(const float4*)(pA + d0 + q*4);
                float f0, f1, f2, f3;
                if (mode == 0) { f0 = a.x; f1 = a.y; f2 = a.z; f3 = a.w; }
                else {
                    float4 bv = *(const float4*)(pB + d0 + q*4);
                    if (mode == 1) { f0 = a.x*bv.x; f1 = a.y*bv.y; f2 = a.z*bv.z; f3 = a.w*bv.w; }
                    else { f0 = (a.x-bv.x)*inv; f1 = (a.y-bv.y)*inv; f2 = (a.z-bv.z)*inv; f3 = (a.w-bv.w)*inv; }
                }
                uint32_t h0, l0, h1, l1;
                split2(f0, f1, h0, l0);
                split2(f2, f3, h1, l1);
                int o = row*AST + colp0 + q*2;
                sAh[o] = h0; sAh[o+1] = h1;
                sAl[o] = l0; sAl[o+1] = l1;
            }
        }
        __syncthreads();
        // MMA: per kt load all fragments once, run 3 passes from registers
        #pragma unroll
        for (int kt = 0; kt < 4; ++kt) {
            const uint32_t off = kt*32;
            uint32_t ah0[4], ah1[4], al0[4], al1[4];
            uint32_t bh0[4], bh1[4], bl0[4], bl1[4];
            ldmx4(ah0, aAh0 + off); ldmx4(ah1, aAh1 + off);
            ldmx4(al0, aAl0 + off); ldmx4(al1, aAl1 + off);
            ldmx4(bh0, aBh0 + off); ldmx4(bh1, aBh1 + off);
            ldmx4(bl0, aBl0 + off); ldmx4(bl1, aBl1 + off);
            uint32_t bh[4][2] = {{bh0[0],bh0[2]},{bh0[1],bh0[3]},{bh1[0],bh1[2]},{bh1[1],bh1[3]}};
            uint32_t bl[4][2] = {{bl0[0],bl0[2]},{bl0[1],bl0[3]},{bl1[0],bl1[2]},{bl1[1],bl1[3]}};
            #pragma unroll
            for (int ni = 0; ni < 4; ++ni) {
                mma16816(acc[0][ni], ah0, bh[ni][0], bh[ni][1]);
                mma16816(acc[1][ni], ah1, bh[ni][0], bh[ni][1]);
                mma16816(acc[0][ni], ah0, bl[ni][0], bl[ni][1]);
                mma16816(acc[1][ni], ah1, bl[ni][0], bl[ni][1]);
                mma16816(acc[0][ni], al0, bh[ni][0], bh[ni][1]);
                mma16816(acc[1][ni], al1, bh[ni][0], bh[ni][1]);
            }
        }
    }

    // ======== bias + gelu -> sHf (fp32, aliases sA region) ========
    __syncthreads();
    #pragma unroll
    for (int mi = 0; mi < 2; ++mi) {
        #pragma unroll
        for (int ni = 0; ni < 4; ++ni) {
            int col = nbase + ni*8 + tg*2;
            int r0 = mbase + mi*16 + g;
            sHf[r0*68 + col]       = gelu_f(acc[mi][ni][0] + sb1[col]);
            sHf[r0*68 + col + 1]   = gelu_f(acc[mi][ni][1] + sb1[col+1]);
            sHf[(r0+8)*68 + col]   = gelu_f(acc[mi][ni][2] + sb1[col]);
            sHf[(r0+8)*68 + col+1] = gelu_f(acc[mi][ni][3] + sb1[col+1]);
        }
    }
    __syncthreads();

    // ======== layer 2 (scalar fp32, split across row-pair threads) ========
    {
        const int row2 = tid >> 1;
        const int ub = half*32;          // this thread's 32 units
        float h2[32] = {};
        #pragma unroll 4
        for (int k = 0; k < 64; ++k) {
            float a = sHf[row2*68 + k];
            const float4* wp = (const float4*)&sW2T[k*64 + ub];
            #pragma unroll
            for (int uq = 0; uq < 8; ++uq) {
                float4 w = wp[uq];
                h2[uq*4+0] += a*w.x;
                h2[uq*4+1] += a*w.y;
                h2[uq*4+2] += a*w.z;
                h2[uq*4+3] += a*w.w;
            }
        }
        #pragma unroll
        for (int u = 0; u < 32; ++u) h2[u] = gelu_f(h2[u] + sb2[ub + u]);
        __syncthreads();                 // all L2 reads of sHf done
        #pragma unroll
        for (int u = 0; u < 32; ++u) sHf[row2*68 + ub + u] = h2[u];
        __syncthreads();                 // h2 visible to partner thread

        // ======== layer 3 (scalar fp32) ========
        const int ob = half*8;
        float o8[8];
        #pragma unroll
        for (int o = 0; o < 8; ++o) o8[o] = sb3[ob + o];
        #pragma unroll 8
        for (int k = 0; k < 64; ++k) {
            float a = sHf[row2*68 + k];
            const float4* wp = (const float4*)&sW3T[k*16 + ob];
            float4 w0 = wp[0], w1 = wp[1];
            o8[0] += a*w0.x; o8[1] += a*w0.y; o8[2] += a*w0.z; o8[3] += a*w0.w;
            o8[4] += a*w1.x; o8[5] += a*w1.y; o8[6] += a*w1.z; o8[7] += a*w1.w;
        }
        int base = sOut[row2];
        #pragma unroll
        for (int o = 0; o < 8; ++o)
            g_Spre[base + (ob + o)*262144] = o8[o];
    }
}

// ---------------- conv1: 16 -> 48, 3x3, pad 2, + GELU (2 px/thread, const-tile skip) ----------------
// grid (17, 33, 8): z = b*4 + g (12 oc per group). Tile 16y x 32x.
__global__ __launch_bounds__(256) void conv1_kernel(
    const float* __restrict__ cw1, const float* __restrict__ cb1)
{
    extern __shared__ float smem[];
    float* sIn = smem;                 // [16][18][35]
    float* sW  = smem + 16*18*35;      // [12][16][9]
    const int tid = threadIdx.x;
    const int b = blockIdx.z >> 2, gg = blockIdx.z & 3;
    const int by = blockIdx.y, bx = blockIdx.x;
    const int ty = tid >> 4, tx = tid & 15;
    const int oy = by*16 + ty;
    const int ox0 = bx*32 + tx*2;

    // const tile: whole 3x3 window (pad=2 conv) above the lower triangle -> inputs all zero
    if (by*16 + 15 <= bx*32 - 3) {
        if (oy < 514 && ox0 < 514) {
            #pragma unroll
            for (int oc = 0; oc < 12; ++oc) {
                int oco = gg*12 + oc;
                float gv = gelu_f(cb1[oco]);
                long base = ((long)(b*48 + oco)*514 + oy)*516 + ox0;
                *(float2*)&g_H1[base] = make_float2(gv, gv);
            }
        }
        return;
    }

    for (int idx = tid; idx < 16*18*34; idx += 256) {
        int c  = idx / 612;
        int rem = idx - c*612;
        int sy = rem / 34, sx = rem - sy*34;
        int iy = by*16 + sy - 2;
        int ix = bx*32 + sx - 2;
        float v = 0.f;
        if (iy >= 0 && iy < 512 && ix >= 0 && ix < 512 && iy >= ix)
            v = g_Spre[((b*16 + c) << 18) + (iy << 9) + ix];
        sIn[(c*18 + sy)*35 + sx] = v;
    }
    for (int idx = tid; idx < 12*16*9; idx += 256)
        sW[idx] = cw1[gg*12*144 + idx];
    __syncthreads();

    float acc[12][2] = {};
    #pragma unroll 1
    for (int c = 0; c < 16; ++c) {
        #pragma unroll
        for (int ky = 0; ky < 3; ++ky) {
            const float* rp = &sIn[(c*18 + ty + ky)*35 + tx*2];
            float vv[4];
            #pragma unroll
            for (int m = 0; m < 4; ++m) vv[m] = rp[m];
            #pragma unroll
            for (int kx = 0; kx < 3; ++kx) {
                #pragma unroll
                for (int oc = 0; oc < 12; ++oc) {
                    float w = sW[(oc*16 + c)*9 + ky*3 + kx];
                    acc[oc][0] += w*vv[kx+0];
                    acc[oc][1] += w*vv[kx+1];
                }
            }
        }
    }
    if (oy < 514 && ox0 < 514) {
        #pragma unroll
        for (int oc = 0; oc < 12; ++oc) {
            int oco = gg*12 + oc;
            float bias = cb1[oco];
            long base = ((long)(b*48 + oco)*514 + oy)*516 + ox0;
            *(float2*)&g_H1[base] = make_float2(
                gelu_f(acc[oc][0] + bias), gelu_f(acc[oc][1] + bias));
        }
    }
}

// ---------------- conv2: 48 -> 16, 3x3 valid, + bias + length-scale + store (2 px/thread, const-tile skip) ----------------
// grid (16, 32, 2): z = b. Tile 16y x 32x of 512x512.
__global__ __launch_bounds__(256) void conv2_kernel(
    const float* __restrict__ cw2, const float* __restrict__ cb2,
    float* __restrict__ out)
{
    extern __shared__ float smem[];
    float* sIn = smem;                 // [12][18][35]
    float* sW  = smem + 12*18*35;      // [16][48][9]
    const int tid = threadIdx.x;
    const int b = blockIdx.z;
    const int by = blockIdx.y, bx = blockIdx.x;
    const int ty = tid >> 4, tx = tid & 15;
    const int oy = by*16 + ty;
    const int ox0 = bx*32 + tx*2;

    // const tile: every H1 value in every window is the const gelu(cb1) value
    if (by*16 + 15 <= bx*32 - 5) {
        float k2[16];
        #pragma unroll
        for (int oc = 0; oc < 16; ++oc) k2[oc] = g_K2[oc];
        #pragma unroll
        for (int px = 0; px < 2; ++px) {
            int ox = ox0 + px;
            int ad = ox - oy;            // upper triangle: ox > oy here
            if (ad < 1) ad = 1;
            float len = (float)ad;
            float4* ob = (float4*)(out + ((long)(oy*512 + ox)*2 + b)*16);
            ob[0] = make_float4(len*k2[0],  len*k2[1],  len*k2[2],  len*k2[3]);
            ob[1] = make_float4(len*k2[4],  len*k2[5],  len*k2[6],  len*k2[7]);
            ob[2] = make_float4(len*k2[8],  len*k2[9],  len*k2[10], len*k2[11]);
            ob[3] = make_float4(len*k2[12], len*k2[13], len*k2[14], len*k2[15]);
        }
        return;
    }

    for (int idx = tid; idx < 16*48*9; idx += 256) sW[idx] = cw2[idx];

    float acc[16][2] = {};
    for (int cc = 0; cc < 4; ++cc) {
        __syncthreads();
        for (int idx = tid; idx < 12*18*34; idx += 256) {
            int c  = idx / 612;
            int rem = idx - c*612;
            int sy = rem / 34, sx = rem - sy*34;
            sIn[(c*18 + sy)*35 + sx] =
                g_H1[((long)(b*48 + cc*12 + c)*514 + by*16 + sy)*516 + bx*32 + sx];
        }
        __syncthreads();
        #pragma unroll 1
        for (int c = 0; c < 12; ++c) {
            #pragma unroll
            for (int ky = 0; ky < 3; ++ky) {
                const float* rp = &sIn[(c*18 + ty + ky)*35 + tx*2];
                float vv[4];
                #pragma unroll
                for (int m = 0; m < 4; ++m) vv[m] = rp[m];
                #pragma unroll
                for (int kx = 0; kx < 3; ++kx) {
                    #pragma unroll
                    for (int oc = 0; oc < 16; ++oc) {
                        float w = sW[(oc*48 + cc*12 + c)*9 + ky*3 + kx];
                        acc[oc][0] += w*vv[kx+0];
                        acc[oc][1] += w*vv[kx+1];
                    }
                }
            }
        }
    }
    float bias[16];
    #pragma unroll
    for (int oc = 0; oc < 16; ++oc) bias[oc] = cb2[oc];
    #pragma unroll
    for (int px = 0; px < 2; ++px) {
        int ox = ox0 + px;
        int ad = oy - ox; if (ad < 0) ad = -ad; if (ad < 1) ad = 1;
        float len = (float)ad;
        float o[16];
        #pragma unroll
        for (int oc = 0; oc < 16; ++oc) o[oc] = len*(acc[oc][px] + bias[oc]);
        float4* ob = (float4*)(out + ((long)(oy*512 + ox)*2 + b)*16);
        ob[0] = make_float4(o[0],  o[1],  o[2],  o[3]);
        ob[1] = make_float4(o[4],  o[5],  o[6],  o[7]);
        ob[2] = make_float4(o[8],  o[9],  o[10], o[11]);
        ob[3] = make_float4(o[12], o[13], o[14], o[15]);
    }
}

// ---------------- launch ----------------
extern "C" void kernel_launch(void* const* d_in, const int* in_sizes, int n_in,
                              void* d_out, int out_size)
{
    const float* x   = (const float*)d_in[0];
    const float* w1  = (const float*)d_in[1];
    const float* b1  = (const float*)d_in[2];
    const float* w2  = (const float*)d_in[3];
    const float* b2  = (const float*)d_in[4];
    const float* w3  = (const float*)d_in[5];
    const float* b3  = (const float*)d_in[6];
    const float* sw1 = (const float*)d_in[7];
    const float* sb1 = (const float*)d_in[8];
    const float* sw2 = (const float*)d_in[9];
    const float* sb2 = (const float*)d_in[10];
    const float* sw3 = (const float*)d_in[11];
    const float* sb3 = (const float*)d_in[12];
    const float* cw1 = (const float*)d_in[13];
    const float* cb1 = (const float*)d_in[14];
    const float* cw2 = (const float*)d_in[15];
    const float* cb2 = (const float*)d_in[16];
    float* out = (float*)d_out;

    const int c1_smem = (16*18*35 + 12*16*9)*4;
    const int c2_smem = (12*18*35 + 16*48*9)*4;
    const int mma_smem = MMA_SMEM_U32*4;
    static bool attr_done = false;
    if (!attr_done) {
        cudaFuncSetAttribute(conv1_kernel, cudaFuncAttributeMaxDynamicSharedMemorySize, c1_smem);
        cudaFuncSetAttribute(conv2_kernel, cudaFuncAttributeMaxDynamicSharedMemorySize, c2_smem);
        cudaFuncSetAttribute(pair_mma_kernel, cudaFuncAttributeMaxDynamicSharedMemorySize, mma_smem);
        attr_done = true;
    }

    prefix_kernel<<<1, 256>>>(x);
    prep_w_kernel<<<64, 256>>>(w1, cw2, cb1, cb2);
    pair_mma_kernel<<<PAIR_BLOCKS + SKIP_BLOCKS, 256, mma_smem>>>(
        x, b1, b2, b3, w2, w3, sw1, sb1, sw2, sb2, sw3, sb3, out + S_OUT_SZ);
    conv1_kernel<<<dim3(17, 33, 8), 256, c1_smem>>>(cw1, cb1);
    conv2_kernel<<<dim3(16, 32, 2), 256, c2_smem>>>(cw2, cb2, out);
}

// round 15
// speedup vs baseline: 2.7013x; 1.0140x over previous
#include <cuda_runtime.h>
#include <cuda_bf16.h>
#include <cstdint>
#include <math.h>

// ---------------- problem constants ----------------
#define NN   512
#define CUMSZ (513*256)           // [513][B][D]
#define SPRE_SZ (2*16*512*512)    // [B][O][512][512]
#define H1_SZ   (2*48*514*516)    // [B][CH][514][516]
#define S_OUT_SZ (512*512*2*16)
#define PAIR_ROWS 262656
#define PAIR_BLOCKS (PAIR_ROWS/128)   // 2052
#define SKIP_ROWS 1022
#define SKIP_BLOCKS 16
#define AST 36                       // A/B smem row stride in u32

__device__ float g_cum[3*CUMSZ];
__device__ float g_Spre[SPRE_SZ];
__device__ float g_H1[H1_SZ];
__device__ float g_K2[16];
// prepped w1: bf16 hi/lo, [chunk][hl][n][k]
__device__ __align__(16) __nv_bfloat16 g_w1p[6*2*64*64];

__device__ __forceinline__ float gelu_f(float v) {
    return 0.5f*v*(1.0f + erff(v*0.70710678118654752440f));
}

__device__ __forceinline__ uint32_t smem_u32(const void* p) {
    uint32_t a;
    asm("{ .reg .u64 t; cvta.to.shared.u64 t, %1; cvt.u32.u64 %0, t; }" : "=r"(a) : "l"(p));
    return a;
}

// fast split: truncate to bf16 (PRMT), residual also truncated
__device__ __forceinline__ void split2f(float v0, float v1, uint32_t& hi, uint32_t& lo) {
    uint32_t u0 = __float_as_uint(v0), u1 = __float_as_uint(v1);
    hi = __byte_perm(u0, u1, 0x7632);
    float l0 = v0 - __uint_as_float(u0 & 0xFFFF0000u);
    float l1 = v1 - __uint_as_float(u1 & 0xFFFF0000u);
    lo = __byte_perm(__float_as_uint(l0), __float_as_uint(l1), 0x7632);
}

__device__ __forceinline__ void mma16816(float* d, const uint32_t* a, uint32_t b0, uint32_t b1) {
    asm volatile("mma.sync.aligned.m16n8k16.row.col.f32.bf16.bf16.f32 "
        "{%0,%1,%2,%3}, {%4,%5,%6,%7}, {%8,%9}, {%0,%1,%2,%3};"
        : "+f"(d[0]), "+f"(d[1]), "+f"(d[2]), "+f"(d[3])
        : "r"(a[0]), "r"(a[1]), "r"(a[2]), "r"(a[3]), "r"(b0), "r"(b1));
}

__device__ __forceinline__ void ldmx4(uint32_t* r, uint32_t addr) {
    asm volatile("ldmatrix.sync.aligned.m8n8.x4.shared.b16 {%0,%1,%2,%3}, [%4];"
        : "=r"(r[0]), "=r"(r[1]), "=r"(r[2]), "=r"(r[3]) : "r"(addr));
}

// ---------------- prefix sums of x, x^2, x^3 ----------------
__global__ void prefix_kernel(const float* __restrict__ x) {
    int t = threadIdx.x;
    float s1 = 0.f, s2 = 0.f, s3 = 0.f;
    g_cum[t] = 0.f; g_cum[CUMSZ + t] = 0.f; g_cum[2*CUMSZ + t] = 0.f;
    for (int n = 0; n < NN; ++n) {
        float v = x[n*256 + t];
        float v2 = v*v;
        s1 += v; s2 += v2; s3 += v2*v;
        int o = (n+1)*256 + t;
        g_cum[o] = s1; g_cum[CUMSZ + o] = s2; g_cum[2*CUMSZ + o] = s3;
    }
}

// ---------------- weight prep: w1 fp32 -> bf16 hi/lo (RN); conv2 const K2 ----------------
__global__ void prep_w_kernel(const float* __restrict__ w1,
                              const float* __restrict__ cw2,
                              const float* __restrict__ cb1,
                              const float* __restrict__ cb2) {
    int i0 = blockIdx.x*blockDim.x + threadIdx.x;
    int stride = gridDim.x*blockDim.x;
    for (int idx = i0; idx < 64*768; idx += stride) {
        int n = idx / 768, k = idx % 768;
        int ch = k >> 6, kk = k & 63;
        float v = w1[idx];
        __nv_bfloat16 h = __float2bfloat16(v);
        float hf = __uint_as_float(((uint32_t)__bfloat16_as_ushort(h)) << 16);
        __nv_bfloat16 l = __float2bfloat16(v - hf);
        g_w1p[((ch*2 + 0)*64 + n)*64 + kk] = h;
        g_w1p[((ch*2 + 1)*64 + n)*64 + kk] = l;
    }
    if (blockIdx.x == 0 && threadIdx.x < 16) {
        int oc = threadIdx.x;
        float s = cb2[oc];
        for (int c = 0; c < 48; ++c) {
            float g = gelu_f(cb1[c]);
            float ws = 0.f;
            #pragma unroll
            for (int k = 0; k < 9; ++k) ws += cw2[(oc*48 + c)*9 + k];
            s += g*ws;
        }
        g_K2[oc] = s;
    }
}

// ---------------- skip MLP body (scalar, validated; runs on dynamic smem) ----------------
__device__ void skip_body(
    float* dsmf, int sblk,
    const float* __restrict__ x,
    const float* __restrict__ w1, const float* __restrict__ b1,
    const float* __restrict__ w2, const float* __restrict__ b2,
    const float* __restrict__ w3, const float* __restrict__ b3,
    float* __restrict__ outSkip)
{
    float* sAB = dsmf;               // 64*68
    float* sH  = dsmf + 64*68;       // 64*68
    int*   sXI = (int*)(dsmf + 2*64*68);
    int*   sXJ = sXI + 64;
    float* sb1 = (float*)(sXJ + 64);
    float* sb2 = sb1 + 64;
    float* sb3 = sb2 + 64;

    const int tid = threadIdx.x;
    const int ty4 = (tid >> 4) * 4;
    const int tx4 = (tid & 15) * 4;

    if (tid < 64) {
        int r = sblk*64 + tid;
        if (r >= SKIP_ROWS) r = SKIP_ROWS - 1;
        int p = r >> 1, b = r & 1;
        sXI[tid] = p*256 + b*128;
        sXJ[tid] = (p+1)*256 + b*128;
        sb1[tid] = b1[tid];
        sb2[tid] = b2[tid];
        if (tid < 16) sb3[tid] = b3[tid];
    }
    __syncthreads();

    float acc[4][4] = {};
    for (int kc = 0; kc < 12; ++kc) {
        const int k0  = kc*32;
        const int seg = k0 >> 7;
        const int d0  = k0 & 127;
        if (kc) __syncthreads();
        #pragma unroll
        for (int e = 0; e < 8; ++e) {
            int idx = tid + e*256;
            int rw = idx >> 5, kk = idx & 31;
            int d = d0 + kk;
            float v;
            if (seg == 0)      v = x[sXI[rw] + d];
            else if (seg == 1) v = x[sXJ[rw] + d];
            else               v = x[sXI[rw] + d] * x[sXJ[rw] + d];
            sAB[kk*68 + rw] = v;
        }
        #pragma unroll
        for (int e = 0; e < 8; ++e) {
            int idx = tid + e*256;
            int col = idx >> 5, kk = idx & 31;
            sAB[(32+kk)*68 + col] = w1[col*384 + k0 + kk];
        }
        __syncthreads();
        #pragma unroll
        for (int kk = 0; kk < 32; ++kk) {
            float4 a  = *(const float4*)&sAB[kk*68 + ty4];
            float4 bv = *(const float4*)&sAB[(32+kk)*68 + tx4];
            acc[0][0] += a.x*bv.x; acc[0][1] += a.x*bv.y; acc[0][2] += a.x*bv.z; acc[0][3] += a.x*bv.w;
            acc[1][0] += a.y*bv.x; acc[1][1] += a.y*bv.y; acc[1][2] += a.y*bv.z; acc[1][3] += a.y*bv.w;
            acc[2][0] += a.z*bv.x; acc[2][1] += a.z*bv.y; acc[2][2] += a.z*bv.z; acc[2][3] += a.z*bv.w;
            acc[3][0] += a.w*bv.x; acc[3][1] += a.w*bv.y; acc[3][2] += a.w*bv.z; acc[3][3] += a.w*bv.w;
        }
    }
    __syncthreads();
    #pragma unroll
    for (int c = 0; c < 4; ++c) {
        float bias = sb1[tx4 + c];
        #pragma unroll
        for (int r = 0; r < 4; ++r)
            sH[(tx4 + c)*68 + ty4 + r] = gelu_f(acc[r][c] + bias);
    }
    #pragma unroll
    for (int e = 0; e < 16; ++e) {
        int idx = tid + e*256;
        int col = idx >> 6, kk = idx & 63;
        sAB[kk*68 + col] = w2[col*64 + kk];
    }
    __syncthreads();
    float acc2[4][4] = {};
    #pragma unroll
    for (int kk = 0; kk < 64; ++kk) {
        float4 a  = *(const float4*)&sH [kk*68 + ty4];
        float4 bv = *(const float4*)&sAB[kk*68 + tx4];
        acc2[0][0] += a.x*bv.x; acc2[0][1] += a.x*bv.y; acc2[0][2] += a.x*bv.z; acc2[0][3] += a.x*bv.w;
        acc2[1][0] += a.y*bv.x; acc2[1][1] += a.y*bv.y; acc2[1][2] += a.y*bv.z; acc2[1][3] += a.y*bv.w;
        acc2[2][0] += a.z*bv.x; acc2[2][1] += a.z*bv.y; acc2[2][2] += a.z*bv.z; acc2[2][3] += a.z*bv.w;
        acc2[3][0] += a.w*bv.x; acc2[3][1] += a.w*bv.y; acc2[3][2] += a.w*bv.z; acc2[3][3] += a.w*bv.w;
    }
    __syncthreads();
    #pragma unroll
    for (int c = 0; c < 4; ++c) {
        float bias = sb2[tx4 + c];
        #pragma unroll
        for (int r = 0; r < 4; ++r)
            sH[(tx4 + c)*68 + ty4 + r] = gelu_f(acc2[r][c] + bias);
    }
    #pragma unroll
    for (int e = 0; e < 4; ++e) {
        int idx = tid + e*256;
        int col = idx & 15, kk = idx >> 4;
        sAB[kk*16 + col] = w3[col*64 + kk];
    }
    __syncthreads();
    const int rw = tid >> 2;
    const int cg  = (tid & 3)*4;
    float o4[4] = {};
    #pragma unroll
    for (int kk = 0; kk < 64; ++kk) {
        float a   = sH[kk*68 + rw];
        float4 wv = *(const float4*)&sAB[kk*16 + cg];
        o4[0] += a*wv.x; o4[1] += a*wv.y; o4[2] += a*wv.z; o4[3] += a*wv.w;
    }
    int rg = sblk*64 + rw;
    if (rg < SKIP_ROWS) {
        #pragma unroll
        for (int c = 0; c < 4; ++c)
            outSkip[rg*16 + cg + c] = o4[c] + sb3[cg + c];
    }
}

// ---------------- pair MLP: HMMA layer 1 (ldmatrix) + scalar fp32 layers 2-3 (+ skip tail) ----------------
// smem u32 offsets
#define O_AH 0
#define O_AL (O_AH + 128*AST)
#define O_BH (O_AL + 128*AST)
#define O_BL (O_BH + 64*AST)
#define O_XI (O_BL + 64*AST)
#define O_XJ (O_XI + 128)
#define O_CI (O_XJ + 128)
#define O_CJ (O_CI + 128)
#define O_OUT (O_CJ + 128)
#define O_INV (O_OUT + 128)
#define O_B1 (O_INV + 128)
#define O_B2 (O_B1 + 64)
#define O_B3 (O_B2 + 64)
#define O_W2T (O_B3 + 16)          // fp32 [k][64]  (4096)
#define O_W3T (O_W2T + 4096)       // fp32 [k][16]  (1024)
#define MMA_SMEM_U32 (O_W3T + 1024)

__global__ __launch_bounds__(256) void pair_mma_kernel(
    const float* __restrict__ x,
    const float* __restrict__ b1, const float* __restrict__ b2, const float* __restrict__ b3,
    const float* __restrict__ w2, const float* __restrict__ w3,
    const float* __restrict__ sw1, const float* __restrict__ sb1v,
    const float* __restrict__ sw2, const float* __restrict__ sb2v,
    const float* __restrict__ sw3, const float* __restrict__ sb3v,
    float* __restrict__ outSkip)
{
    extern __shared__ uint32_t sm[];

    if (blockIdx.x >= PAIR_BLOCKS) {    // uniform per block
        skip_body((float*)sm, blockIdx.x - PAIR_BLOCKS,
                  x, sw1, sb1v, sw2, sb2v, sw3, sb3v, outSkip);
        return;
    }

    uint32_t* sAh = sm + O_AH;
    uint32_t* sAl = sm + O_AL;
    uint32_t* sBh = sm + O_BH;
    uint32_t* sBl = sm + O_BL;
    float* sHf = (float*)(sm + O_AH);   // alias: fp32 H [128][68] after L1 (and h2 after L2)
    int*   sXI = (int*)(sm + O_XI);
    int*   sXJ = (int*)(sm + O_XJ);
    int*   sCI = (int*)(sm + O_CI);
    int*   sCJ = (int*)(sm + O_CJ);
    int*   sOut = (int*)(sm + O_OUT);
    float* sInv = (float*)(sm + O_INV);
    float* sb1 = (float*)(sm + O_B1);
    float* sb2 = (float*)(sm + O_B2);
    float* sb3 = (float*)(sm + O_B3);
    float* sW2T = (float*)(sm + O_W2T);
    float* sW3T = (float*)(sm + O_W3T);

    const int tid = threadIdx.x;
    const int wid = tid >> 5;
    const int lane = tid & 31;
    const int g = lane >> 2;
    const int tg = lane & 3;
    const int wm = wid & 3;
    const int wn = wid >> 2;
    const int mbase = wm*32;
    const int nbase = wn*32;

    if (tid < 128) {
        int r = blockIdx.x*128 + tid;
        int p = r >> 1, b = r & 1;
        int i = (int)((sqrt(8.0*(double)p + 1.0) - 1.0)*0.5);
        while ((i+1)*(i+2)/2 <= p) ++i;
        while (i*(i+1)/2 > p) --i;
        int j = p - i*(i+1)/2;
        sXI[tid] = i*256 + b*128;
        sXJ[tid] = j*256 + b*128;
        sCI[tid] = (i+1)*256 + b*128;
        sCJ[tid] = j*256 + b*128;
        sInv[tid] = 1.0f/(float)(i - j + 1);
        sOut[tid] = b*4194304 + i*512 + j;
    }
    if (tid < 64) { sb1[tid] = b1[tid]; sb2[tid] = b2[tid]; }
    if (tid >= 64 && tid < 80) sb3[tid - 64] = b3[tid - 64];
    // load w2/w3 transposed (fp32): sW2T[k*64+u] = w2[u*64+k]
    for (int idx = tid; idx < 4096; idx += 256) {
        int u = idx >> 6, k = idx & 63;
        sW2T[k*64 + u] = w2[idx];
    }
    for (int idx = tid; idx < 1024; idx += 256) {
        int u = idx >> 6, k = idx & 63;
        sW3T[k*16 + u] = w3[idx];
    }

    // ldmatrix lane base addresses (bytes)
    const uint32_t smb = smem_u32(sm);
    const int wi8 = lane & 7, quad = lane >> 3;
    const uint32_t laneoff = (uint32_t)(((wi8 + (quad & 1)*8)*AST + (quad >> 1)*4) * 4);
    const uint32_t aAh0 = smb + (uint32_t)(O_AH + mbase*AST)*4 + laneoff;
    const uint32_t aAh1 = aAh0 + 16*AST*4;
    const uint32_t aAl0 = aAh0 + (uint32_t)(O_AL - O_AH)*4;
    const uint32_t aAl1 = aAl0 + 16*AST*4;
    const uint32_t aBh0 = smb + (uint32_t)(O_BH + nbase*AST)*4 + laneoff;
    const uint32_t aBh1 = aBh0 + 16*AST*4;
    const uint32_t aBl0 = aBh0 + (uint32_t)(O_BL - O_BH)*4;
    const uint32_t aBl1 = aBl0 + 16*AST*4;

    float acc[2][4][4] = {};

    // ======== layer 1 (HMMA + ldmatrix): K = 768, 12 chunks of 64 ========
    const int row = tid >> 1;
    const int half = tid & 1;
    for (int ch = 0; ch < 12; ++ch) {
        __syncthreads();
        // w1 chunk (hi/lo) -> sB, vectorized uint4
        {
            const uint4* src = (const uint4*)(((const uint32_t*)g_w1p) + ch*4096);
            #pragma unroll
            for (int it = 0; it < 2; ++it) {
                int i4 = tid + it*256;            // 0..511
                int n = i4 >> 3, kw = (i4 & 7)*4;
                *(uint4*)&sBh[n*AST + kw] = src[i4];
                *(uint4*)&sBl[n*AST + kw] = src[i4 + 512];
            }
        }
        // features for this chunk -> sA (hi/lo), fast truncation split
        {
            int seg = ch >> 1;
            int d0 = (ch & 1)*64 + half*32;
            int colp0 = half*16;
            const float* pA; const float* pB = nullptr; float inv = 1.f;
            int mode;
            if (seg == 0)      { pA = x + sXI[row]; mode = 0; }
            else if (seg == 1) { pA = x + sXJ[row]; mode = 0; }
            else if (seg == 2) { pA = x + sXI[row]; pB = x + sXJ[row]; mode = 1; }
            else {
                const float* c0 = g_cum + (seg - 3)*CUMSZ;
                pA = c0 + sCI[row]; pB = c0 + sCJ[row]; inv = sInv[row]; mode = 2;
            }
            #pragma unroll
            for (int q = 0; q < 8; ++q) {
                float4 a = *(const float4*)(pA + d0 + q*4);
                float f0, f1, f2, f3;
                if (mode == 0) { f0 = a.x; f1 = a.y; f2 = a.z; f3 = a.w; }
                else {
                    float4 bv = *(const float4*)(pB + d0 + q*4);
                    if (mode == 1) { f0 = a.x*bv.x; f1 = a.y*bv.y; f2 = a.z*bv.z; f3 = a.w*bv.w; }
                    else { f0 = (a.x-bv.x)*inv; f1 = (a.y-bv.y)*inv; f2 = (a.z-bv.z)*inv; f3 = (a.w-bv.w)*inv; }
                }
                uint32_t h0, l0, h1, l1;
                split2f(f0, f1, h0, l0);
                split2f(f2, f3, h1, l1);
                int o = row*AST + colp0 + q*2;
                sAh[o] = h0; sAh[o+1] = h1;
                sAl[o] = l0; sAl[o+1] = l1;
            }
        }
        __syncthreads();
        // MMA: per kt load all fragments once, run 3 passes from registers
        #pragma unroll
        for (int kt = 0; kt < 4; ++kt) {
            const uint32_t off = kt*32;
            uint32_t ah0[4], ah1[4], al0[4], al1[4];
            uint32_t bh0[4], bh1[4], bl0[4], bl1[4];
            ldmx4(ah0, aAh0 + off); ldmx4(ah1, aAh1 + off);
            ldmx4(al0, aAl0 + off); ldmx4(al1, aAl1 + off);
            ldmx4(bh0, aBh0 + off); ldmx4(bh1, aBh1 + off);
            ldmx4(bl0, aBl0 + off); ldmx4(bl1, aBl1 + off);
            uint32_t bh[4][2] = {{bh0[0],bh0[2]},{bh0[1],bh0[3]},{bh1[0],bh1[2]},{bh1[1],bh1[3]}};
            uint32_t bl[4][2] = {{bl0[0],bl0[2]},{bl0[1],bl0[3]},{bl1[0],bl1[2]},{bl1[1],bl1[3]}};
            #pragma unroll
            for (int ni = 0; ni < 4; ++ni) {
                mma16816(acc[0][ni], ah0, bh[ni][0], bh[ni][1]);
                mma16816(acc[1][ni], ah1, bh[ni][0], bh[ni][1]);
                mma16816(acc[0][ni], ah0, bl[ni][0], bl[ni][1]);
                mma16816(acc[1][ni], ah1, bl[ni][0], bl[ni][1]);
                mma16816(acc[0][ni], al0, bh[ni][0], bh[ni][1]);
                mma16816(acc[1][ni], al1, bh[ni][0], bh[ni][1]);
            }
        }
    }

    // ======== bias + gelu -> sHf (fp32, aliases sA region) ========
    __syncthreads();
    #pragma unroll
    for (int mi = 0; mi < 2; ++mi) {
        #pragma unroll
        for (int ni = 0; ni < 4; ++ni) {
            int col = nbase + ni*8 + tg*2;
            int r0 = mbase + mi*16 + g;
            sHf[r0*68 + col]       = gelu_f(acc[mi][ni][0] + sb1[col]);
            sHf[r0*68 + col + 1]   = gelu_f(acc[mi][ni][1] + sb1[col+1]);
            sHf[(r0+8)*68 + col]   = gelu_f(acc[mi][ni][2] + sb1[col]);
            sHf[(r0+8)*68 + col+1] = gelu_f(acc[mi][ni][3] + sb1[col+1]);
        }
    }
    __syncthreads();

    // ======== layer 2 (scalar fp32, split across row-pair threads) ========
    {
        const int row2 = tid >> 1;
        const int ub = half*32;          // this thread's 32 units
        float h2[32] = {};
        #pragma unroll 4
        for (int k = 0; k < 64; ++k) {
            float a = sHf[row2*68 + k];
            const float4* wp = (const float4*)&sW2T[k*64 + ub];
            #pragma unroll
            for (int uq = 0; uq < 8; ++uq) {
                float4 w = wp[uq];
                h2[uq*4+0] += a*w.x;
                h2[uq*4+1] += a*w.y;
                h2[uq*4+2] += a*w.z;
                h2[uq*4+3] += a*w.w;
            }
        }
        #pragma unroll
        for (int u = 0; u < 32; ++u) h2[u] = gelu_f(h2[u] + sb2[ub + u]);
        __syncthreads();                 // all L2 reads of sHf done
        #pragma unroll
        for (int u = 0; u < 32; ++u) sHf[row2*68 + ub + u] = h2[u];
        __syncthreads();                 // h2 visible to partner thread

        // ======== layer 3 (scalar fp32) ========
        const int ob = half*8;
        float o8[8];
        #pragma unroll
        for (int o = 0; o < 8; ++o) o8[o] = sb3[ob + o];
        #pragma unroll 8
        for (int k = 0; k < 64; ++k) {
            float a = sHf[row2*68 + k];
            const float4* wp = (const float4*)&sW3T[k*16 + ob];
            float4 w0 = wp[0], w1 = wp[1];
            o8[0] += a*w0.x; o8[1] += a*w0.y; o8[2] += a*w0.z; o8[3] += a*w0.w;
            o8[4] += a*w1.x; o8[5] += a*w1.y; o8[6] += a*w1.z; o8[7] += a*w1.w;
        }
        int base = sOut[row2];
        #pragma unroll
        for (int o = 0; o < 8; ++o)
            g_Spre[base + (ob + o)*262144] = o8[o];
    }
}

// ---------------- conv1: 16 -> 48, 3x3, pad 2, + GELU (4px x 6oc per thread) ----------------
// grid (17, 33, 8): z = b*4 + g (12 oc per group). Tile 16y x 32x. 256 thr = 16y x 8x x 2oc-half.
__global__ __launch_bounds__(256) void conv1_kernel(
    const float* __restrict__ cw1, const float* __restrict__ cb1)
{
    extern __shared__ float smem[];
    float* sIn = smem;                 // [16][18][36]
    float* sW  = smem + 16*18*36;      // [12][16][9]
    const int tid = threadIdx.x;
    const int b = blockIdx.z >> 2, gg = blockIdx.z & 3;
    const int by = blockIdx.y, bx = blockIdx.x;
    const int ty = tid >> 4, tq = tid & 15;
    const int oh = tq >> 3, tx = tq & 7;
    const int ocb = oh*6;
    const int oy = by*16 + ty;
    const int ox0 = bx*32 + tx*4;

    // const tile: whole 3x3 window (pad=2 conv) above the lower triangle -> inputs all zero
    if (by*16 + 15 <= bx*32 - 3) {
        if (oy < 514 && ox0 < 514) {
            #pragma unroll
            for (int oc = 0; oc < 6; ++oc) {
                int oco = gg*12 + ocb + oc;
                float gv = gelu_f(cb1[oco]);
                long base = ((long)(b*48 + oco)*514 + oy)*516 + ox0;
                *(float4*)&g_H1[base] = make_float4(gv, gv, gv, gv);
            }
        }
        return;
    }

    for (int idx = tid; idx < 16*18*34; idx += 256) {
        int c  = idx / 612;
        int rem = idx - c*612;
        int sy = rem / 34, sx = rem - sy*34;
        int iy = by*16 + sy - 2;
        int ix = bx*32 + sx - 2;
        float v = 0.f;
        if (iy >= 0 && iy < 512 && ix >= 0 && ix < 512 && iy >= ix)
            v = g_Spre[((b*16 + c) << 18) + (iy << 9) + ix];
        sIn[(c*18 + sy)*36 + sx] = v;
    }
    for (int idx = tid; idx < 12*16*9; idx += 256)
        sW[idx] = cw1[gg*12*144 + idx];
    __syncthreads();

    float acc[6][4] = {};
    #pragma unroll 1
    for (int c = 0; c < 16; ++c) {
        #pragma unroll
        for (int ky = 0; ky < 3; ++ky) {
            const float* rp = &sIn[(c*18 + ty + ky)*36 + tx*4];
            float4 v4 = *(const float4*)rp;
            float vv[6] = {v4.x, v4.y, v4.z, v4.w, rp[4], rp[5]};
            #pragma unroll
            for (int kx = 0; kx < 3; ++kx) {
                #pragma unroll
                for (int oc = 0; oc < 6; ++oc) {
                    float w = sW[((ocb + oc)*16 + c)*9 + ky*3 + kx];
                    acc[oc][0] += w*vv[kx+0];
                    acc[oc][1] += w*vv[kx+1];
                    acc[oc][2] += w*vv[kx+2];
                    acc[oc][3] += w*vv[kx+3];
                }
            }
        }
    }
    if (oy < 514 && ox0 < 514) {
        #pragma unroll
        for (int oc = 0; oc < 6; ++oc) {
            int oco = gg*12 + ocb + oc;
            float bias = cb1[oco];
            long base = ((long)(b*48 + oco)*514 + oy)*516 + ox0;
            *(float4*)&g_H1[base] = make_float4(
                gelu_f(acc[oc][0] + bias), gelu_f(acc[oc][1] + bias),
                gelu_f(acc[oc][2] + bias), gelu_f(acc[oc][3] + bias));
        }
    }
}

// ---------------- conv2: 48 -> 16, 3x3 valid, + bias + length-scale + store (4px x 8oc) ----------------
// grid (16, 32, 2): z = b. Tile 16y x 32x of 512x512. 256 thr = 16y x 8x x 2oc-half.
__global__ __launch_bounds__(256) void conv2_kernel(
    const float* __restrict__ cw2, const float* __restrict__ cb2,
    float* __restrict__ out)
{
    extern __shared__ float smem[];
    float* sIn = smem;                 // [12][18][36]
    float* sW  = smem + 12*18*36;      // [16][48][9]
    const int tid = threadIdx.x;
    const int b = blockIdx.z;
    const int by = blockIdx.y, bx = blockIdx.x;
    const int ty = tid >> 4, tq = tid & 15;
    const int oh = tq >> 3, tx = tq & 7;
    const int ocb = oh*8;
    const int oy = by*16 + ty;
    const int ox0 = bx*32 + tx*4;

    // const tile: every H1 value in every window is the const gelu(cb1) value
    if (by*16 + 15 <= bx*32 - 5) {
        float k2[8];
        #pragma unroll
        for (int oc = 0; oc < 8; ++oc) k2[oc] = g_K2[ocb + oc];
        #pragma unroll
        for (int px = 0; px < 4; ++px) {
            int ox = ox0 + px;
            int ad = ox - oy;            // upper triangle: ox > oy here
            if (ad < 1) ad = 1;
            float len = (float)ad;
            float4* ob = (float4*)(out + ((long)(oy*512 + ox)*2 + b)*16 + ocb);
            ob[0] = make_float4(len*k2[0], len*k2[1], len*k2[2], len*k2[3]);
            ob[1] = make_float4(len*k2[4], len*k2[5], len*k2[6], len*k2[7]);
        }
        return;
    }

    for (int idx = tid; idx < 16*48*9; idx += 256) sW[idx] = cw2[idx];

    float acc[8][4] = {};
    for (int cc = 0; cc < 4; ++cc) {
        __syncthreads();
        for (int idx = tid; idx < 12*18*34; idx += 256) {
            int c  = idx / 612;
            int rem = idx - c*612;
            int sy = rem / 34, sx = rem - sy*34;
            sIn[(c*18 + sy)*36 + sx] =
                g_H1[((long)(b*48 + cc*12 + c)*514 + by*16 + sy)*516 + bx*32 + sx];
        }
        __syncthreads();
        #pragma unroll 1
        for (int c = 0; c < 12; ++c) {
            #pragma unroll
            for (int ky = 0; ky < 3; ++ky) {
                const float* rp = &sIn[(c*18 + ty + ky)*36 + tx*4];
                float4 v4 = *(const float4*)rp;
                float vv[6] = {v4.x, v4.y, v4.z, v4.w, rp[4], rp[5]};
                #pragma unroll
                for (int kx = 0; kx < 3; ++kx) {
                    #pragma unroll
                    for (int oc = 0; oc < 8; ++oc) {
                        float w = sW[((ocb + oc)*48 + cc*12 + c)*9 + ky*3 + kx];
                        acc[oc][0] += w*vv[kx+0];
                        acc[oc][1] += w*vv[kx+1];
                        acc[oc][2] += w*vv[kx+2];
                        acc[oc][3] += w*vv[kx+3];
                    }
                }
            }
        }
    }
    float bias[8];
    #pragma unroll
    for (int oc = 0; oc < 8; ++oc) bias[oc] = cb2[ocb + oc];
    #pragma unroll
    for (int px = 0; px < 4; ++px) {
        int ox = ox0 + px;
        int ad = oy - ox; if (ad < 0) ad = -ad; if (ad < 1) ad = 1;
        float len = (float)ad;
        float o[8];
        #pragma unroll
        for (int oc = 0; oc < 8; ++oc) o[oc] = len*(acc[oc][px] + bias[oc]);
        float4* ob = (float4*)(out + ((long)(oy*512 + ox)*2 + b)*16 + ocb);
        ob[0] = make_float4(o[0], o[1], o[2], o[3]);
        ob[1] = make_float4(o[4], o[5], o[6], o[7]);
    }
}

// ---------------- launch ----------------
extern "C" void kernel_launch(void* const* d_in, const int* in_sizes, int n_in,
                              void* d_out, int out_size)
{
    const float* x   = (const float*)d_in[0];
    const float* w1  = (const float*)d_in[1];
    const float* b1  = (const float*)d_in[2];
    const float* w2  = (const float*)d_in[3];
    const float* b2  = (const float*)d_in[4];
    const float* w3  = (const float*)d_in[5];
    const float* b3  = (const float*)d_in[6];
    const float* sw1 = (const float*)d_in[7];
    const float* sb1 = (const float*)d_in[8];
    const float* sw2 = (const float*)d_in[9];
    const float* sb2 = (const float*)d_in[10];
    const float* sw3 = (const float*)d_in[11];
    const float* sb3 = (const float*)d_in[12];
    const float* cw1 = (const float*)d_in[13];
    const float* cb1 = (const float*)d_in[14];
    const float* cw2 = (const float*)d_in[15];
    const float* cb2 = (const float*)d_in[16];
    float* out = (float*)d_out;

    const int c1_smem = (16*18*36 + 12*16*9)*4;
    const int c2_smem = (12*18*36 + 16*48*9)*4;
    const int mma_smem = MMA_SMEM_U32*4;
    static bool attr_done = false;
    if (!attr_done) {
        cudaFuncSetAttribute(conv1_kernel, cudaFuncAttributeMaxDynamicSharedMemorySize, c1_smem);
        cudaFuncSetAttribute(conv2_kernel, cudaFuncAttributeMaxDynamicSharedMemorySize, c2_smem);
        cudaFuncSetAttribute(pair_mma_kernel, cudaFuncAttributeMaxDynamicSharedMemorySize, mma_smem);
        attr_done = true;
    }

    prefix_kernel<<<1, 256>>>(x);
    prep_w_kernel<<<64, 256>>>(w1, cw2, cb1, cb2);
    pair_mma_kernel<<<PAIR_BLOCKS + SKIP_BLOCKS, 256, mma_smem>>>(
        x, b1, b2, b3, w2, w3, sw1, sb1, sw2, sb2, sw3, sb3, out + S_OUT_SZ);
    conv1_kernel<<<dim3(17, 33, 8), 256, c1_smem>>>(cw1, cb1);
    conv2_kernel<<<dim3(16, 32, 2), 256, c2_smem>>>(cw2, cb2, out);
}